// round 1
// baseline (speedup 1.0000x reference)
#include <cuda_runtime.h>
#include <math.h>

#define NL 4
#define NB 2
#define NS 1024
#define ND 1024
#define NH 16
#define NDH 64
#define NTOK (NB*NS)        // 2048
#define ATT_SCALE 0.125f    // 1/sqrt(64)
#define LN_EPS 1e-5f

// ---------------- scratch (static device globals: alloc-free) ----------------
__device__ float g_x    [NTOK*ND];          // residual stream
__device__ float g_h    [NTOK*ND];          // LN output / GEMM input
__device__ float g_x1p  [NTOK*ND];
__device__ float g_x2p  [NTOK*ND];
__device__ float g_qkv1 [NTOK*3*ND];
__device__ float g_qkv2 [NTOK*3*ND];
__device__ float g_vavg [NTOK*ND];
__device__ float g_s1   [(size_t)NB*NH*NS*NS];   // 134 MB
__device__ float g_s2   [(size_t)NB*NH*NS*NS];   // 134 MB
__device__ float g_attno[NTOK*ND];
__device__ float g_tmp  [NTOK*ND];
__device__ float g_mlp  [NTOK*4*ND];
__device__ float g_adapt[ND];

// ---------------- helpers ----------------
template<bool MAXRED>
__device__ __forceinline__ float blk_reduce(float v, float* red) {
    int t = threadIdx.x;           // blockDim.x == 256
    red[t] = v; __syncthreads();
    #pragma unroll
    for (int o = 128; o > 0; o >>= 1) {
        if (t < o) red[t] = MAXRED ? fmaxf(red[t], red[t + o]) : (red[t] + red[t + o]);
        __syncthreads();
    }
    float r = red[0];
    __syncthreads();
    return r;
}

// ---------------- tiny kernels ----------------
__global__ void copy_kernel(const float* __restrict__ in, float* __restrict__ out, int n) {
    int i = blockIdx.x * 256 + threadIdx.x;
    if (i < n) out[i] = in[i];
}

// adapt[i] = sigma * sum_r U[i][r] * (sum_j V[r][j])
__global__ void adapt_kernel(const float* __restrict__ U, const float* __restrict__ V,
                             const float* __restrict__ sigma, float* __restrict__ adapt) {
    __shared__ float red[256];
    __shared__ float vsum[4];
    int t = threadIdx.x;
    for (int r = 0; r < 4; r++) {
        float s = 0.f;
        for (int j = t; j < ND; j += 256) s += V[r * ND + j];
        s = blk_reduce<false>(s, red);
        if (t == 0) vsum[r] = s;
        __syncthreads();
    }
    float sg = sigma[0];
    for (int i = t; i < ND; i += 256) {
        float a = 0.f;
        #pragma unroll
        for (int r = 0; r < 4; r++) a += U[i * 4 + r] * vsum[r];
        adapt[i] = a * sg;
    }
}

// out = [res +] LN(in; g,b) [+ adapt]    (one block per token row, 256 thr, D=1024)
template<bool ADD_ADAPT, bool RES>
__global__ void ln_kernel(const float* __restrict__ in, const float* __restrict__ g,
                          const float* __restrict__ b, const float* __restrict__ adapt,
                          const float* __restrict__ res, float* __restrict__ out) {
    __shared__ float red[256];
    int row = blockIdx.x, t = threadIdx.x;
    const float* rin = in + (size_t)row * ND;
    float v[4];
    #pragma unroll
    for (int i = 0; i < 4; i++) v[i] = rin[t + i * 256];
    float s = v[0] + v[1] + v[2] + v[3];
    float mean = blk_reduce<false>(s, red) * (1.0f / ND);
    float sq = 0.f;
    #pragma unroll
    for (int i = 0; i < 4; i++) { float d = v[i] - mean; sq += d * d; }
    float var = blk_reduce<false>(sq, red) * (1.0f / ND);
    float inv = rsqrtf(var + LN_EPS);
    #pragma unroll
    for (int i = 0; i < 4; i++) {
        int c = t + i * 256;
        float o = (v[i] - mean) * inv * g[c] + b[c];
        if (ADD_ADAPT) o += adapt[c];
        if (RES)       o += res[(size_t)row * ND + c];
        out[(size_t)row * ND + c] = o;
    }
}

// ---------------- generic SGEMM: C = A[M,K](lda) @ B[K,N] (+bias) (+res) (gelu) ----------------
template<bool GELU, bool RES>
__global__ void __launch_bounds__(256) sgemm_kernel(
    const float* __restrict__ A, int lda,
    const float* __restrict__ B, const float* __restrict__ bias,
    const float* __restrict__ res, float* __restrict__ C,
    int M, int N, int K)
{
    __shared__ float As[8][128];
    __shared__ float Bs[8][132];
    int t = threadIdx.x;
    int m0 = blockIdx.y * 128, n0 = blockIdx.x * 128;
    int arow = t >> 1, ak = (t & 1) * 4;
    int bk = t >> 5, bcol = (t & 31) * 4;
    const float* Aptr = A + (size_t)(m0 + arow) * lda + ak;
    const float* Bptr = B + (size_t)bk * N + n0 + bcol;
    int ty = t >> 4, tx = t & 15;
    float acc[8][8] = {};

    for (int kt = 0; kt < K; kt += 8) {
        float4 av = *(const float4*)(Aptr + kt);
        float4 bv = *(const float4*)(Bptr + (size_t)kt * N);
        As[ak + 0][arow] = av.x; As[ak + 1][arow] = av.y;
        As[ak + 2][arow] = av.z; As[ak + 3][arow] = av.w;
        *(float4*)&Bs[bk][bcol] = bv;
        __syncthreads();
        #pragma unroll
        for (int k = 0; k < 8; k++) {
            float a[8], bb[8];
            float4 a0 = *(const float4*)&As[k][ty * 8];
            float4 a1 = *(const float4*)&As[k][ty * 8 + 4];
            float4 b0 = *(const float4*)&Bs[k][tx * 8];
            float4 b1 = *(const float4*)&Bs[k][tx * 8 + 4];
            a[0]=a0.x; a[1]=a0.y; a[2]=a0.z; a[3]=a0.w; a[4]=a1.x; a[5]=a1.y; a[6]=a1.z; a[7]=a1.w;
            bb[0]=b0.x; bb[1]=b0.y; bb[2]=b0.z; bb[3]=b0.w; bb[4]=b1.x; bb[5]=b1.y; bb[6]=b1.z; bb[7]=b1.w;
            #pragma unroll
            for (int i = 0; i < 8; i++)
                #pragma unroll
                for (int j = 0; j < 8; j++)
                    acc[i][j] += a[i] * bb[j];
        }
        __syncthreads();
    }
    #pragma unroll
    for (int i = 0; i < 8; i++) {
        int row = m0 + ty * 8 + i;
        #pragma unroll
        for (int j = 0; j < 8; j++) {
            int col = n0 + tx * 8 + j;
            float v = acc[i][j];
            if (bias) v += bias[col];
            if (RES)  v += res[(size_t)row * N + col];
            if (GELU) v = 0.5f * v * (1.0f + erff(v * 0.70710678118654752f));
            C[(size_t)row * N + col] = v;
        }
    }
}

// ---------------- attention scores: S[z,q,k] = SCALE * Q[z,q,:] . K[z,k,:]  (DH=64) ----------------
__global__ void __launch_bounds__(256) scores_kernel(const float* __restrict__ qkv, float* __restrict__ out) {
    __shared__ float Qs[64][68];
    __shared__ float Ks[64][68];
    int z = blockIdx.z;                 // b*16 + h
    int b = z >> 4, h = z & 15;
    int bq = blockIdx.y * 64, bk = blockIdx.x * 64;
    int t = threadIdx.x;
    int r = t >> 4, c = (t & 15) * 4;
    const float* qbase = qkv + ((size_t)(b * NS + bq)) * 3072 + h * 64;
    const float* kbase = qkv + ((size_t)(b * NS + bk)) * 3072 + ND + h * 64;
    #pragma unroll
    for (int rr = 0; rr < 64; rr += 16) {
        float4 qv = *(const float4*)(qbase + (size_t)(r + rr) * 3072 + c);
        float4 kv = *(const float4*)(kbase + (size_t)(r + rr) * 3072 + c);
        *(float4*)&Qs[r + rr][c] = qv;
        *(float4*)&Ks[r + rr][c] = kv;
    }
    __syncthreads();
    int ty = t >> 4, tx = t & 15;
    float acc[4][4] = {};
    #pragma unroll
    for (int k = 0; k < 64; k += 4) {
        float a[4][4], bb[4][4];
        #pragma unroll
        for (int i = 0; i < 4; i++) {
            float4 av = *(const float4*)&Qs[ty * 4 + i][k];
            a[i][0]=av.x; a[i][1]=av.y; a[i][2]=av.z; a[i][3]=av.w;
        }
        #pragma unroll
        for (int j = 0; j < 4; j++) {
            float4 bv = *(const float4*)&Ks[tx * 4 + j][k];
            bb[j][0]=bv.x; bb[j][1]=bv.y; bb[j][2]=bv.z; bb[j][3]=bv.w;
        }
        #pragma unroll
        for (int i = 0; i < 4; i++)
            #pragma unroll
            for (int j = 0; j < 4; j++)
                #pragma unroll
                for (int kk = 0; kk < 4; kk++)
                    acc[i][j] += a[i][kk] * bb[j][kk];
    }
    #pragma unroll
    for (int i = 0; i < 4; i++)
        #pragma unroll
        for (int j = 0; j < 4; j++)
            out[((size_t)z * NS + bq + ty * 4 + i) * NS + bk + tx * 4 + j] = acc[i][j] * ATT_SCALE;
}

// ---------------- dual softmax + diff (in place into s1): s1 = softmax(s1) - softmax(s2) ----------------
__global__ void softmax_diff_kernel(float* __restrict__ s1, const float* __restrict__ s2) {
    __shared__ float red[256];
    size_t row = blockIdx.x;
    float* r1 = s1 + row * NS;
    const float* r2 = s2 + row * NS;
    int t = threadIdx.x;
    float v1[4], v2[4];
    #pragma unroll
    for (int i = 0; i < 4; i++) { v1[i] = r1[t + i * 256]; v2[i] = r2[t + i * 256]; }
    float m1 = fmaxf(fmaxf(v1[0], v1[1]), fmaxf(v1[2], v1[3]));
    float m2 = fmaxf(fmaxf(v2[0], v2[1]), fmaxf(v2[2], v2[3]));
    m1 = blk_reduce<true>(m1, red);
    m2 = blk_reduce<true>(m2, red);
    float e1 = 0.f, e2 = 0.f;
    #pragma unroll
    for (int i = 0; i < 4; i++) {
        v1[i] = __expf(v1[i] - m1); e1 += v1[i];
        v2[i] = __expf(v2[i] - m2); e2 += v2[i];
    }
    e1 = blk_reduce<false>(e1, red);
    e2 = blk_reduce<false>(e2, red);
    float i1 = 1.0f / e1, i2 = 1.0f / e2;
    #pragma unroll
    for (int i = 0; i < 4; i++) r1[t + i * 256] = v1[i] * i1 - v2[i] * i2;
}

// ---------------- vavg[tok,c] = 0.5*(v1 + v2) ----------------
__global__ void vavg_kernel(const float* __restrict__ q1, const float* __restrict__ q2,
                            float* __restrict__ out) {
    int i = blockIdx.x * 256 + threadIdx.x;   // over NTOK*ND
    int tok = i >> 10, c = i & 1023;
    size_t src = (size_t)tok * 3072 + 2048 + c;
    out[i] = 0.5f * (q1[src] + q2[src]);
}

// ---------------- PV: O[b, q, h*64+d] = sum_k Diff[z,q,k] * Vavg[b,k,h*64+d] ----------------
__global__ void __launch_bounds__(256) pv_kernel(const float* __restrict__ Dm,
                                                 const float* __restrict__ Vm,
                                                 float* __restrict__ Om) {
    __shared__ float Ds[64][36];
    __shared__ float Vs[32][68];
    int q0 = blockIdx.x * 64;
    int z = blockIdx.y;
    int b = z >> 4, h = z & 15;
    int t = threadIdx.x;
    int ty = t >> 4, tx = t & 15;
    int drow = t >> 2, dcol = (t & 3) * 8;
    int vrow = t >> 3, vcol = (t & 7) * 8;
    const float* dbase = Dm + ((size_t)z * NS + q0) * NS;
    const float* vbase = Vm + (size_t)(b * NS) * ND + h * 64;
    float acc[4][4] = {};
    for (int kc = 0; kc < NS; kc += 32) {
        float4 d0 = *(const float4*)(dbase + (size_t)drow * NS + kc + dcol);
        float4 d1 = *(const float4*)(dbase + (size_t)drow * NS + kc + dcol + 4);
        float4 v0 = *(const float4*)(vbase + (size_t)(kc + vrow) * ND + vcol);
        float4 v1 = *(const float4*)(vbase + (size_t)(kc + vrow) * ND + vcol + 4);
        *(float4*)&Ds[drow][dcol]     = d0;
        *(float4*)&Ds[drow][dcol + 4] = d1;
        *(float4*)&Vs[vrow][vcol]     = v0;
        *(float4*)&Vs[vrow][vcol + 4] = v1;
        __syncthreads();
        #pragma unroll
        for (int k = 0; k < 32; k += 4) {
            float a[4][4], bb[4][4];
            #pragma unroll
            for (int i = 0; i < 4; i++) {
                float4 av = *(const float4*)&Ds[ty * 4 + i][k];
                a[i][0]=av.x; a[i][1]=av.y; a[i][2]=av.z; a[i][3]=av.w;
            }
            #pragma unroll
            for (int kk = 0; kk < 4; kk++) {
                float4 bv = *(const float4*)&Vs[k + kk][tx * 4];
                bb[kk][0]=bv.x; bb[kk][1]=bv.y; bb[kk][2]=bv.z; bb[kk][3]=bv.w;
            }
            #pragma unroll
            for (int i = 0; i < 4; i++)
                #pragma unroll
                for (int kk = 0; kk < 4; kk++)
                    #pragma unroll
                    for (int j = 0; j < 4; j++)
                        acc[i][j] += a[i][kk] * bb[kk][j];
        }
        __syncthreads();
    }
    #pragma unroll
    for (int i = 0; i < 4; i++)
        #pragma unroll
        for (int j = 0; j < 4; j++)
            Om[((size_t)(b * NS + q0 + ty * 4 + i)) * ND + h * 64 + tx * 4 + j] = acc[i][j];
}

// ---------------- host orchestration ----------------
extern "C" void kernel_launch(void* const* d_in, const int* in_sizes, int n_in,
                              void* d_out, int out_size) {
    (void)in_sizes; (void)n_in; (void)out_size;
    const float* x     = (const float*)d_in[0];
    const float* sigma = (const float*)d_in[1];
    const float* U     = (const float*)d_in[2];
    const float* V     = (const float*)d_in[3];
    const float* Wqkv1 = (const float*)d_in[4];
    const float* Wqkv2 = (const float*)d_in[5];
    const float* Wp1   = (const float*)d_in[6];
    const float* bp1   = (const float*)d_in[7];
    const float* Wp2   = (const float*)d_in[8];
    const float* bp2   = (const float*)d_in[9];
    const float* Wo    = (const float*)d_in[10];
    const float* bo    = (const float*)d_in[11];
    const float* gO    = (const float*)d_in[12];
    const float* bO    = (const float*)d_in[13];
    const float* g1    = (const float*)d_in[14];
    const float* b1    = (const float*)d_in[15];
    const float* g2    = (const float*)d_in[16];
    const float* b2    = (const float*)d_in[17];
    const float* Wm1   = (const float*)d_in[18];
    const float* bm1   = (const float*)d_in[19];
    const float* Wm2   = (const float*)d_in[20];
    const float* bm2   = (const float*)d_in[21];
    const float* gf    = (const float*)d_in[22];
    const float* bf    = (const float*)d_in[23];

    float *px, *ph, *px1, *px2, *pq1, *pq2, *pva, *ps1, *ps2, *pat, *ptmp, *pmlp, *pad;
    cudaGetSymbolAddress((void**)&px,  g_x);
    cudaGetSymbolAddress((void**)&ph,  g_h);
    cudaGetSymbolAddress((void**)&px1, g_x1p);
    cudaGetSymbolAddress((void**)&px2, g_x2p);
    cudaGetSymbolAddress((void**)&pq1, g_qkv1);
    cudaGetSymbolAddress((void**)&pq2, g_qkv2);
    cudaGetSymbolAddress((void**)&pva, g_vavg);
    cudaGetSymbolAddress((void**)&ps1, g_s1);
    cudaGetSymbolAddress((void**)&ps2, g_s2);
    cudaGetSymbolAddress((void**)&pat, g_attno);
    cudaGetSymbolAddress((void**)&ptmp, g_tmp);
    cudaGetSymbolAddress((void**)&pmlp, g_mlp);
    cudaGetSymbolAddress((void**)&pad, g_adapt);

    copy_kernel<<<NTOK * ND / 256, 256>>>(x, px, NTOK * ND);

    for (int l = 0; l < NL; l++) {
        adapt_kernel<<<1, 256>>>(U + (size_t)l * ND * 4, V + (size_t)l * 4 * ND, sigma + l, pad);
        ln_kernel<true, false><<<NTOK, 256>>>(px, g1 + l * ND, b1 + l * ND, pad, nullptr, ph);

        // x1p = a[:, :512] @ Wp1 + bp1 ; x2p = a[:, 512:] @ Wp2 + bp2
        sgemm_kernel<false, false><<<dim3(8, 16), 256>>>(ph,       ND, Wp1 + (size_t)l * 512 * ND, bp1 + l * ND, nullptr, px1, NTOK, ND, 512);
        sgemm_kernel<false, false><<<dim3(8, 16), 256>>>(ph + 512, ND, Wp2 + (size_t)l * 512 * ND, bp2 + l * ND, nullptr, px2, NTOK, ND, 512);

        // qkv = x?p @ Wqkv?
        sgemm_kernel<false, false><<<dim3(24, 16), 256>>>(px1, ND, Wqkv1 + (size_t)l * ND * 3 * ND, nullptr, nullptr, pq1, NTOK, 3 * ND, ND);
        sgemm_kernel<false, false><<<dim3(24, 16), 256>>>(px2, ND, Wqkv2 + (size_t)l * ND * 3 * ND, nullptr, nullptr, pq2, NTOK, 3 * ND, ND);

        // attention
        scores_kernel<<<dim3(16, 16, 32), 256>>>(pq1, ps1);
        scores_kernel<<<dim3(16, 16, 32), 256>>>(pq2, ps2);
        softmax_diff_kernel<<<NB * NH * NS, 256>>>(ps1, ps2);
        vavg_kernel<<<NTOK * ND / 256, 256>>>(pq1, pq2, pva);
        pv_kernel<<<dim3(16, 32), 256>>>(ps1, pva, pat);

        // out proj + post-LN + residual
        sgemm_kernel<false, false><<<dim3(8, 16), 256>>>(pat, ND, Wo + (size_t)l * ND * ND, bo + l * ND, nullptr, ptmp, NTOK, ND, ND);
        ln_kernel<false, true><<<NTOK, 256>>>(ptmp, gO + l * ND, bO + l * ND, nullptr, px, px);

        // MLP
        ln_kernel<false, false><<<NTOK, 256>>>(px, g2 + l * ND, b2 + l * ND, nullptr, nullptr, ph);
        sgemm_kernel<true, false><<<dim3(32, 16), 256>>>(ph, ND, Wm1 + (size_t)l * ND * 4 * ND, bm1 + (size_t)l * 4 * ND, nullptr, pmlp, NTOK, 4 * ND, ND);
        sgemm_kernel<false, true><<<dim3(8, 16), 256>>>(pmlp, 4 * ND, Wm2 + (size_t)l * 4 * ND * ND, bm2 + l * ND, px, px, NTOK, ND, 4 * ND);
    }

    ln_kernel<false, false><<<NTOK, 256>>>(px, gf, bf, nullptr, nullptr, (float*)d_out);
}

// round 4
// speedup vs baseline: 2.2378x; 2.2378x over previous
#include <cuda_runtime.h>
#include <cuda_fp16.h>
#include <math.h>
#include <stdint.h>

#define NL 4
#define NB 2
#define NS 1024
#define ND 1024
#define NH 16
#define NDH 64
#define NTOK (NB*NS)        // 2048
#define ATT_SCALE 0.125f
#define LN_EPS 1e-5f

// ---------------- scratch (static device globals: alloc-free) ----------------
__device__ float g_x    [NTOK*ND];
__device__ float g_h    [NTOK*ND];
__device__ float g_x1p  [NTOK*ND];
__device__ float g_x2p  [NTOK*ND];
__device__ float g_qkv1 [NTOK*3*ND];
__device__ float g_qkv2 [NTOK*3*ND];
__device__ float g_vavg [32*NS*NDH];             // [z][k][64]
__device__ float g_s1   [(size_t)NB*NH*NS*NS];   // 134 MB
__device__ float g_s2   [(size_t)NB*NH*NS*NS];   // 134 MB
__device__ float g_attno[NTOK*ND];
__device__ float g_tmp  [NTOK*ND];
__device__ float g_mlp  [NTOK*4*ND];
__device__ float g_adapt[ND];

// ---------------- helpers ----------------
__device__ __forceinline__ uint32_t smem_u32(const void* p) {
    uint32_t a;
    asm("{ .reg .u64 t; cvta.to.shared.u64 t, %1; cvt.u32.u64 %0, t; }" : "=r"(a) : "l"(p));
    return a;
}

// split two floats into packed fp16x2 hi and lo words
__device__ __forceinline__ void split2(float x, float y, uint32_t& hi, uint32_t& lo) {
    __half hx = __float2half_rn(x), hy = __float2half_rn(y);
    float rx = x - __half2float(hx), ry = y - __half2float(hy);
    __half lx = __float2half_rn(rx), ly = __float2half_rn(ry);
    hi = (uint32_t)__half_as_ushort(hx) | ((uint32_t)__half_as_ushort(hy) << 16);
    lo = (uint32_t)__half_as_ushort(lx) | ((uint32_t)__half_as_ushort(ly) << 16);
}

__device__ __forceinline__ void mma16(float* c, const uint32_t* a, const uint32_t* b) {
    asm volatile(
        "mma.sync.aligned.m16n8k16.row.col.f32.f16.f16.f32 "
        "{%0,%1,%2,%3},{%4,%5,%6,%7},{%8,%9},{%0,%1,%2,%3};\n"
        : "+f"(c[0]), "+f"(c[1]), "+f"(c[2]), "+f"(c[3])
        : "r"(a[0]), "r"(a[1]), "r"(a[2]), "r"(a[3]), "r"(b[0]), "r"(b[1]));
}

__device__ __forceinline__ void ldsm4t(uint32_t* r, uint32_t addr) {
    asm volatile("ldmatrix.sync.aligned.m8n8.x4.trans.shared.b16 {%0,%1,%2,%3}, [%4];"
        : "=r"(r[0]), "=r"(r[1]), "=r"(r[2]), "=r"(r[3]) : "r"(addr));
}

template<bool MAXRED>
__device__ __forceinline__ float blk_reduce(float v, float* red) {
    int t = threadIdx.x;  // blockDim.x == 256
    red[t] = v; __syncthreads();
    #pragma unroll
    for (int o = 128; o > 0; o >>= 1) {
        if (t < o) red[t] = MAXRED ? fmaxf(red[t], red[t + o]) : (red[t] + red[t + o]);
        __syncthreads();
    }
    float r = red[0];
    __syncthreads();
    return r;
}

// ---------------- tiny kernels ----------------
__global__ void copy_kernel(const float* __restrict__ in, float* __restrict__ out, int n) {
    int i = blockIdx.x * 256 + threadIdx.x;
    if (i < n) out[i] = in[i];
}

__global__ void adapt_kernel(const float* __restrict__ U, const float* __restrict__ V,
                             const float* __restrict__ sigma, float* __restrict__ adapt) {
    __shared__ float red[256];
    __shared__ float vsum[4];
    int t = threadIdx.x;
    for (int r = 0; r < 4; r++) {
        float s = 0.f;
        for (int j = t; j < ND; j += 256) s += V[r * ND + j];
        s = blk_reduce<false>(s, red);
        if (t == 0) vsum[r] = s;
        __syncthreads();
    }
    float sg = sigma[0];
    for (int i = t; i < ND; i += 256) {
        float a = 0.f;
        #pragma unroll
        for (int r = 0; r < 4; r++) a += U[i * 4 + r] * vsum[r];
        adapt[i] = a * sg;
    }
}

template<bool ADD_ADAPT, bool RES>
__global__ void ln_kernel(const float* __restrict__ in, const float* __restrict__ g,
                          const float* __restrict__ b, const float* __restrict__ adapt,
                          const float* __restrict__ res, float* __restrict__ out) {
    __shared__ float red[256];
    int row = blockIdx.x, t = threadIdx.x;
    const float* rin = in + (size_t)row * ND;
    float v[4];
    #pragma unroll
    for (int i = 0; i < 4; i++) v[i] = rin[t + i * 256];
    float s = v[0] + v[1] + v[2] + v[3];
    float mean = blk_reduce<false>(s, red) * (1.0f / ND);
    float sq = 0.f;
    #pragma unroll
    for (int i = 0; i < 4; i++) { float d = v[i] - mean; sq += d * d; }
    float var = blk_reduce<false>(sq, red) * (1.0f / ND);
    float inv = rsqrtf(var + LN_EPS);
    #pragma unroll
    for (int i = 0; i < 4; i++) {
        int c = t + i * 256;
        float o = (v[i] - mean) * inv * g[c] + b[c];
        if (ADD_ADAPT) o += adapt[c];
        if (RES)       o += res[(size_t)row * ND + c];
        out[(size_t)row * ND + c] = o;
    }
}

// s1 = softmax(s1) - softmax(s2), row-wise over NS
__global__ void softmax_diff_kernel(float* __restrict__ s1, const float* __restrict__ s2) {
    __shared__ float red[256];
    size_t row = blockIdx.x;
    float* r1 = s1 + row * NS;
    const float* r2 = s2 + row * NS;
    int t = threadIdx.x;
    float v1[4], v2[4];
    #pragma unroll
    for (int i = 0; i < 4; i++) { v1[i] = r1[t + i * 256]; v2[i] = r2[t + i * 256]; }
    float m1 = fmaxf(fmaxf(v1[0], v1[1]), fmaxf(v1[2], v1[3]));
    float m2 = fmaxf(fmaxf(v2[0], v2[1]), fmaxf(v2[2], v2[3]));
    m1 = blk_reduce<true>(m1, red);
    m2 = blk_reduce<true>(m2, red);
    float e1 = 0.f, e2 = 0.f;
    #pragma unroll
    for (int i = 0; i < 4; i++) {
        v1[i] = __expf(v1[i] - m1); e1 += v1[i];
        v2[i] = __expf(v2[i] - m2); e2 += v2[i];
    }
    e1 = blk_reduce<false>(e1, red);
    e2 = blk_reduce<false>(e2, red);
    float i1 = 1.0f / e1, i2 = 1.0f / e2;
    #pragma unroll
    for (int i = 0; i < 4; i++) r1[t + i * 256] = v1[i] * i1 - v2[i] * i2;
}

// vavg[z][k][d] = 0.5*(v1 + v2)   (head-major layout for PV GEMM)
__global__ void vavg_kernel(const float* __restrict__ q1, const float* __restrict__ q2,
                            float* __restrict__ out) {
    int i = blockIdx.x * 256 + threadIdx.x;  // over 32*NS*64 = 2M
    int d = i & 63;
    int k = (i >> 6) & (NS - 1);
    int z = i >> 16;
    int b = z >> 4, h = z & 15;
    size_t src = ((size_t)(b * NS + k)) * 3072 + 2048 + h * 64 + d;
    out[i] = 0.5f * (q1[src] + q2[src]);
}

// ---------------- split-fp16 tensor-core GEMM ----------------
// C[M,N] = alpha * A[M,K] @ op(B) (+bias)(+res)(gelu), fp32-grade accuracy via
// 2-term fp16 operand split: C = Ah*Bh + Ah*Bl + Al*Bh.
// TRANSB=false: B is [K,N] row-major.  TRANSB=true: B is [N,K] row-major.
// Batch: per blockIdx.z, offset = (z>>4)*Outer + (z&15)*Inner.
// BM=128, BK=32, BN in {128,64}. 256 threads.
template<int BN, bool TRANSB, bool GELU, bool RES>
__global__ void __launch_bounds__(256) mma_gemm(
    const float* __restrict__ A, int lda, long long aO, long long aI,
    const float* __restrict__ B, int ldb, long long bO, long long bI,
    const float* __restrict__ bias, const float* __restrict__ res,
    float* __restrict__ C, int ldc, long long cO, long long cI,
    int M, int N, int K, float alpha)
{
    constexpr int AP = 40;                         // A smem half-stride (32 + 8 pad)
    constexpr int BROWS = TRANSB ? BN : 32;
    constexpr int BP    = TRANSB ? 40 : (BN + 8);  // B smem half-stride
    __shared__ unsigned short Ah[128 * AP], Al[128 * AP];
    __shared__ unsigned short Bh[BROWS * BP], Bl[BROWS * BP];

    const int t = threadIdx.x;
    const int w = t >> 5, lane = t & 31;
    const int g = lane >> 2, th = lane & 3;
    const int m0 = blockIdx.y * 128, n0 = blockIdx.x * BN;
    const int z = blockIdx.z;
    const long long offA = (long long)(z >> 4) * aO + (long long)(z & 15) * aI;
    const long long offB = (long long)(z >> 4) * bO + (long long)(z & 15) * bI;
    const long long offC = (long long)(z >> 4) * cO + (long long)(z & 15) * cI;
    const float* Ag = A + offA;
    const float* Bg = B + offB;

    // warp tiling
    constexpr int MFRAG = (BN == 128) ? 4 : 2;  // warp tile 64x32 or 32x32
    const int wm = (BN == 128) ? ((w >> 2) * 64) : ((w >> 1) * 32);
    const int wn = (BN == 128) ? ((w & 3) * 32) : ((w & 1) * 32);

    // ldmatrix lane roles (weights path)
    const int lrow = (lane & 7) + ((lane & 8) ? 8 : 0);
    const int lcol = (lane & 16) ? 8 : 0;
    const uint32_t bh_base = smem_u32(Bh);
    const uint32_t bl_base = smem_u32(Bl);

    float acc[MFRAG][4][4] = {};

    for (int kt = 0; kt < K; kt += 32) {
        // ---- stage A tile 128x32 (split fp16) ----
        {
            int c4 = (t & 7) * 4;
            #pragma unroll
            for (int it = 0; it < 4; it++) {
                int r = (t >> 3) + it * 32;
                float4 v = *(const float4*)(Ag + (size_t)(m0 + r) * lda + kt + c4);
                uint32_t h0, l0, h1, l1;
                split2(v.x, v.y, h0, l0);
                split2(v.z, v.w, h1, l1);
                *(uint32_t*)&Ah[r * AP + c4]     = h0;
                *(uint32_t*)&Ah[r * AP + c4 + 2] = h1;
                *(uint32_t*)&Al[r * AP + c4]     = l0;
                *(uint32_t*)&Al[r * AP + c4 + 2] = l1;
            }
        }
        // ---- stage B tile ----
        if (TRANSB) {
            // B[N][K] -> Bs[n][k]
            int kc4 = (t & 7) * 4;
            #pragma unroll
            for (int it = 0; it < BN / 32; it++) {
                int n = (t >> 3) + it * 32;
                float4 v = *(const float4*)(Bg + (size_t)(n0 + n) * ldb + kt + kc4);
                uint32_t h0, l0, h1, l1;
                split2(v.x, v.y, h0, l0);
                split2(v.z, v.w, h1, l1);
                *(uint32_t*)&Bh[n * BP + kc4]     = h0;
                *(uint32_t*)&Bh[n * BP + kc4 + 2] = h1;
                *(uint32_t*)&Bl[n * BP + kc4]     = l0;
                *(uint32_t*)&Bl[n * BP + kc4 + 2] = l1;
            }
        } else if (BN == 128) {
            // B[K][N] -> Bs[k][n]
            int nc = (t & 31) * 4;
            #pragma unroll
            for (int it = 0; it < 4; it++) {
                int kr = (t >> 5) + it * 8;
                float4 v = *(const float4*)(Bg + (size_t)(kt + kr) * ldb + n0 + nc);
                uint32_t h0, l0, h1, l1;
                split2(v.x, v.y, h0, l0);
                split2(v.z, v.w, h1, l1);
                *(uint32_t*)&Bh[kr * BP + nc]     = h0;
                *(uint32_t*)&Bh[kr * BP + nc + 2] = h1;
                *(uint32_t*)&Bl[kr * BP + nc]     = l0;
                *(uint32_t*)&Bl[kr * BP + nc + 2] = l1;
            }
        } else {  // BN == 64
            int nc = (t & 15) * 4;
            #pragma unroll
            for (int it = 0; it < 2; it++) {
                int kr = (t >> 4) + it * 16;
                float4 v = *(const float4*)(Bg + (size_t)(kt + kr) * ldb + n0 + nc);
                uint32_t h0, l0, h1, l1;
                split2(v.x, v.y, h0, l0);
                split2(v.z, v.w, h1, l1);
                *(uint32_t*)&Bh[kr * BP + nc]     = h0;
                *(uint32_t*)&Bh[kr * BP + nc + 2] = h1;
                *(uint32_t*)&Bl[kr * BP + nc]     = l0;
                *(uint32_t*)&Bl[kr * BP + nc + 2] = l1;
            }
        }
        __syncthreads();

        // ---- compute: 2 k-steps of 16 ----
        #pragma unroll
        for (int ks = 0; ks < 2; ks++) {
            int ko = ks * 16;
            // B fragments (hi and lo)
            uint32_t bh[4][2], bl[4][2];
            if (TRANSB) {
                #pragma unroll
                for (int ni = 0; ni < 4; ni++) {
                    int n = wn + ni * 8 + g;
                    bh[ni][0] = *(const uint32_t*)&Bh[n * BP + ko + 2 * th];
                    bh[ni][1] = *(const uint32_t*)&Bh[n * BP + ko + 8 + 2 * th];
                    bl[ni][0] = *(const uint32_t*)&Bl[n * BP + ko + 2 * th];
                    bl[ni][1] = *(const uint32_t*)&Bl[n * BP + ko + 8 + 2 * th];
                }
            } else {
                #pragma unroll
                for (int pr = 0; pr < 2; pr++) {
                    uint32_t off = (uint32_t)(((ko + lrow) * BP + wn + pr * 16 + lcol) * 2);
                    uint32_t r[4];
                    ldsm4t(r, bh_base + off);
                    bh[pr*2][0] = r[0]; bh[pr*2][1] = r[1]; bh[pr*2+1][0] = r[2]; bh[pr*2+1][1] = r[3];
                    ldsm4t(r, bl_base + off);
                    bl[pr*2][0] = r[0]; bl[pr*2][1] = r[1]; bl[pr*2+1][0] = r[2]; bl[pr*2+1][1] = r[3];
                }
            }
            // A hi fragments; hi*hi + hi*lo
            uint32_t af[MFRAG][4];
            #pragma unroll
            for (int mi = 0; mi < MFRAG; mi++) {
                int mr = wm + mi * 16 + g;
                af[mi][0] = *(const uint32_t*)&Ah[(mr    ) * AP + ko + 2 * th];
                af[mi][1] = *(const uint32_t*)&Ah[(mr + 8) * AP + ko + 2 * th];
                af[mi][2] = *(const uint32_t*)&Ah[(mr    ) * AP + ko + 8 + 2 * th];
                af[mi][3] = *(const uint32_t*)&Ah[(mr + 8) * AP + ko + 8 + 2 * th];
            }
            #pragma unroll
            for (int mi = 0; mi < MFRAG; mi++)
                #pragma unroll
                for (int ni = 0; ni < 4; ni++) {
                    mma16(acc[mi][ni], af[mi], bh[ni]);
                    mma16(acc[mi][ni], af[mi], bl[ni]);
                }
            // A lo fragments; lo*hi
            #pragma unroll
            for (int mi = 0; mi < MFRAG; mi++) {
                int mr = wm + mi * 16 + g;
                af[mi][0] = *(const uint32_t*)&Al[(mr    ) * AP + ko + 2 * th];
                af[mi][1] = *(const uint32_t*)&Al[(mr + 8) * AP + ko + 2 * th];
                af[mi][2] = *(const uint32_t*)&Al[(mr    ) * AP + ko + 8 + 2 * th];
                af[mi][3] = *(const uint32_t*)&Al[(mr + 8) * AP + ko + 8 + 2 * th];
            }
            #pragma unroll
            for (int mi = 0; mi < MFRAG; mi++)
                #pragma unroll
                for (int ni = 0; ni < 4; ni++)
                    mma16(acc[mi][ni], af[mi], bh[ni]);
        }
        __syncthreads();
    }

    // ---- epilogue ----
    float* Cg = C + offC;
    #pragma unroll
    for (int mi = 0; mi < MFRAG; mi++) {
        #pragma unroll
        for (int ni = 0; ni < 4; ni++) {
            int col = n0 + wn + ni * 8 + th * 2;
            #pragma unroll
            for (int half = 0; half < 2; half++) {
                int row = m0 + wm + mi * 16 + g + half * 8;
                float v0 = acc[mi][ni][half * 2 + 0] * alpha;
                float v1 = acc[mi][ni][half * 2 + 1] * alpha;
                if (bias) { v0 += bias[col]; v1 += bias[col + 1]; }
                if (RES) {
                    v0 += res[(size_t)row * ldc + col];
                    v1 += res[(size_t)row * ldc + col + 1];
                }
                if (GELU) {
                    v0 = 0.5f * v0 * (1.0f + erff(v0 * 0.70710678118654752f));
                    v1 = 0.5f * v1 * (1.0f + erff(v1 * 0.70710678118654752f));
                }
                *(float2*)(Cg + (size_t)row * ldc + col) = make_float2(v0, v1);
            }
        }
    }
}

// ---------------- host orchestration ----------------
extern "C" void kernel_launch(void* const* d_in, const int* in_sizes, int n_in,
                              void* d_out, int out_size) {
    (void)in_sizes; (void)n_in; (void)out_size;
    const float* x     = (const float*)d_in[0];
    const float* sigma = (const float*)d_in[1];
    const float* U     = (const float*)d_in[2];
    const float* V     = (const float*)d_in[3];
    const float* Wqkv1 = (const float*)d_in[4];
    const float* Wqkv2 = (const float*)d_in[5];
    const float* Wp1   = (const float*)d_in[6];
    const float* bp1   = (const float*)d_in[7];
    const float* Wp2   = (const float*)d_in[8];
    const float* bp2   = (const float*)d_in[9];
    const float* Wo    = (const float*)d_in[10];
    const float* bo    = (const float*)d_in[11];
    const float* gO    = (const float*)d_in[12];
    const float* bO    = (const float*)d_in[13];
    const float* g1    = (const float*)d_in[14];
    const float* b1    = (const float*)d_in[15];
    const float* g2    = (const float*)d_in[16];
    const float* b2    = (const float*)d_in[17];
    const float* Wm1   = (const float*)d_in[18];
    const float* bm1   = (const float*)d_in[19];
    const float* Wm2   = (const float*)d_in[20];
    const float* bm2   = (const float*)d_in[21];
    const float* gf    = (const float*)d_in[22];
    const float* bf    = (const float*)d_in[23];

    float *px, *ph, *px1, *px2, *pq1, *pq2, *pva, *ps1, *ps2, *pat, *ptmp, *pmlp, *pad;
    cudaGetSymbolAddress((void**)&px,  g_x);
    cudaGetSymbolAddress((void**)&ph,  g_h);
    cudaGetSymbolAddress((void**)&px1, g_x1p);
    cudaGetSymbolAddress((void**)&px2, g_x2p);
    cudaGetSymbolAddress((void**)&pq1, g_qkv1);
    cudaGetSymbolAddress((void**)&pq2, g_qkv2);
    cudaGetSymbolAddress((void**)&pva, g_vavg);
    cudaGetSymbolAddress((void**)&ps1, g_s1);
    cudaGetSymbolAddress((void**)&ps2, g_s2);
    cudaGetSymbolAddress((void**)&pat, g_attno);
    cudaGetSymbolAddress((void**)&ptmp, g_tmp);
    cudaGetSymbolAddress((void**)&pmlp, g_mlp);
    cudaGetSymbolAddress((void**)&pad, g_adapt);

    copy_kernel<<<NTOK * ND / 256, 256>>>(x, px, NTOK * ND);

    const long long ZA = (long long)NS * 3072;       // qkv batch stride (b)
    const long long ZS = (long long)NS * NS;         // scores batch (z)
    const long long ZV = (long long)NS * NDH;        // vavg batch (z)

    for (int l = 0; l < NL; l++) {
        adapt_kernel<<<1, 256>>>(U + (size_t)l * ND * 4, V + (size_t)l * 4 * ND, sigma + l, pad);
        ln_kernel<true, false><<<NTOK, 256>>>(px, g1 + l * ND, b1 + l * ND, pad, nullptr, ph);

        // x1p = a[:,:512] @ Wp1 + bp1 ; x2p = a[:,512:] @ Wp2 + bp2
        mma_gemm<128, false, false, false><<<dim3(8, 16), 256>>>(
            ph, ND, 0, 0, Wp1 + (size_t)l * 512 * ND, ND, 0, 0,
            bp1 + l * ND, nullptr, px1, ND, 0, 0, NTOK, ND, 512, 1.0f);
        mma_gemm<128, false, false, false><<<dim3(8, 16), 256>>>(
            ph + 512, ND, 0, 0, Wp2 + (size_t)l * 512 * ND, ND, 0, 0,
            bp2 + l * ND, nullptr, px2, ND, 0, 0, NTOK, ND, 512, 1.0f);

        // qkv = x?p @ Wqkv?
        mma_gemm<128, false, false, false><<<dim3(24, 16), 256>>>(
            px1, ND, 0, 0, Wqkv1 + (size_t)l * ND * 3 * ND, 3 * ND, 0, 0,
            nullptr, nullptr, pq1, 3 * ND, 0, 0, NTOK, 3 * ND, ND, 1.0f);
        mma_gemm<128, false, false, false><<<dim3(24, 16), 256>>>(
            px2, ND, 0, 0, Wqkv2 + (size_t)l * ND * 3 * ND, 3 * ND, 0, 0,
            nullptr, nullptr, pq2, 3 * ND, 0, 0, NTOK, 3 * ND, ND, 1.0f);

        // scores: S[z] = scale * Q[z] @ K[z]^T   (z = b*16+h)
        mma_gemm<128, true, false, false><<<dim3(8, 8, 32), 256>>>(
            pq1, 3072, ZA, 64, pq1 + ND, 3072, ZA, 64,
            nullptr, nullptr, ps1, NS, 16 * ZS, ZS, NS, NS, NDH, ATT_SCALE);
        mma_gemm<128, true, false, false><<<dim3(8, 8, 32), 256>>>(
            pq2, 3072, ZA, 64, pq2 + ND, 3072, ZA, 64,
            nullptr, nullptr, ps2, NS, 16 * ZS, ZS, NS, NS, NDH, ATT_SCALE);

        softmax_diff_kernel<<<NB * NH * NS, 256>>>(ps1, ps2);
        vavg_kernel<<<32 * NS * NDH / 256, 256>>>(pq1, pq2, pva);

        // PV: O[z] = Diff[z] @ Vavg[z]  -> written as [b,s,h*64+d]
        mma_gemm<64, false, false, false><<<dim3(1, 8, 32), 256>>>(
            ps1, NS, 16 * ZS, ZS, pva, NDH, 16 * ZV, ZV,
            nullptr, nullptr, pat, ND, (long long)NS * ND, 64, NS, NDH, NS, 1.0f);

        // out proj + post-LN + residual
        mma_gemm<128, false, false, false><<<dim3(8, 16), 256>>>(
            pat, ND, 0, 0, Wo + (size_t)l * ND * ND, ND, 0, 0,
            bo + l * ND, nullptr, ptmp, ND, 0, 0, NTOK, ND, ND, 1.0f);
        ln_kernel<false, true><<<NTOK, 256>>>(ptmp, gO + l * ND, bO + l * ND, nullptr, px, px);

        // MLP
        ln_kernel<false, false><<<NTOK, 256>>>(px, g2 + l * ND, b2 + l * ND, nullptr, nullptr, ph);
        mma_gemm<128, false, true, false><<<dim3(32, 16), 256>>>(
            ph, ND, 0, 0, Wm1 + (size_t)l * ND * 4 * ND, 4 * ND, 0, 0,
            bm1 + (size_t)l * 4 * ND, nullptr, pmlp, 4 * ND, 0, 0, NTOK, 4 * ND, ND, 1.0f);
        mma_gemm<128, false, false, true><<<dim3(8, 16), 256>>>(
            pmlp, 4 * ND, 0, 0, Wm2 + (size_t)l * 4 * ND * ND, ND, 0, 0,
            bm2 + l * ND, px, px, ND, 0, 0, NTOK, ND, 4 * ND, 1.0f);
    }

    ln_kernel<false, false><<<NTOK, 256>>>(px, gf, bf, nullptr, nullptr, (float*)d_out);
}

// round 5
// speedup vs baseline: 2.8777x; 1.2859x over previous
#include <cuda_runtime.h>
#include <cuda_fp16.h>
#include <math.h>
#include <stdint.h>

#define NL 4
#define NB 2
#define NS 1024
#define ND 1024
#define NH 16
#define NDH 64
#define NTOK (NB*NS)        // 2048
#define ATT_SCALE 0.125f
#define LN_EPS 1e-5f

typedef unsigned short u16;

// ---------------- scratch (static device globals: alloc-free) ----------------
__device__ float g_x    [NTOK*ND];
__device__ float g_tmp  [NTOK*ND];
__device__ float g_s1   [(size_t)NB*NH*NS*NS];   // scores fp32 (134 MB)
__device__ float g_s2   [(size_t)NB*NH*NS*NS];
__device__ float g_adapt[ND];

// split fp16 operand buffers (hi, lo)
#define WTOT 67108864ULL     // all weights, 16777216 per layer
__device__ u16 g_wh [WTOT];
__device__ u16 g_wl [WTOT];
__device__ u16 g_hh [NTOK*ND],      g_hl [NTOK*ND];       // LN out
__device__ u16 g_x1h[NTOK*ND],      g_x1l[NTOK*ND];
__device__ u16 g_x2h[NTOK*ND],      g_x2l[NTOK*ND];
__device__ u16 g_q1h[NTOK*3*ND],    g_q1l[NTOK*3*ND];
__device__ u16 g_q2h[NTOK*3*ND],    g_q2l[NTOK*3*ND];
__device__ u16 g_dh [(size_t)32*NS*NS], g_dl[(size_t)32*NS*NS]; // softmax diff
__device__ u16 g_vah[32*NS*NDH],    g_val[32*NS*NDH];
__device__ u16 g_ph [NTOK*ND],      g_pl [NTOK*ND];       // attn out (pat)
__device__ u16 g_mh [NTOK*4*ND],    g_ml [NTOK*4*ND];     // gelu out

// ---------------- helpers ----------------
__device__ __forceinline__ uint32_t smem_u32(const void* p) {
    uint32_t a;
    asm("{ .reg .u64 t; cvta.to.shared.u64 t, %1; cvt.u32.u64 %0, t; }" : "=r"(a) : "l"(p));
    return a;
}
__device__ __forceinline__ void splitw(float v, u16& h, u16& l) {
    __half hh = __float2half_rn(v);
    h = __half_as_ushort(hh);
    l = __half_as_ushort(__float2half_rn(v - __half2float(hh)));
}
__device__ __forceinline__ float joinw(u16 h, u16 l) {
    return __half2float(__ushort_as_half(h)) + __half2float(__ushort_as_half(l));
}
__device__ __forceinline__ void mma16(float* c, const uint32_t* a, const uint32_t* b) {
    asm volatile(
        "mma.sync.aligned.m16n8k16.row.col.f32.f16.f16.f32 "
        "{%0,%1,%2,%3},{%4,%5,%6,%7},{%8,%9},{%0,%1,%2,%3};\n"
        : "+f"(c[0]), "+f"(c[1]), "+f"(c[2]), "+f"(c[3])
        : "r"(a[0]), "r"(a[1]), "r"(a[2]), "r"(a[3]), "r"(b[0]), "r"(b[1]));
}
__device__ __forceinline__ void ldsm4t(uint32_t* r, uint32_t addr) {
    asm volatile("ldmatrix.sync.aligned.m8n8.x4.trans.shared.b16 {%0,%1,%2,%3}, [%4];"
        : "=r"(r[0]), "=r"(r[1]), "=r"(r[2]), "=r"(r[3]) : "r"(addr));
}
__device__ __forceinline__ void cpa16(uint32_t dst, const void* src) {
    asm volatile("cp.async.cg.shared.global [%0], [%1], 16;" :: "r"(dst), "l"(src));
}
__device__ __forceinline__ void cpacommit() { asm volatile("cp.async.commit_group;"); }
template<int N> __device__ __forceinline__ void cpawait() {
    asm volatile("cp.async.wait_group %0;" :: "n"(N));
}

template<bool MAXRED>
__device__ __forceinline__ float blk_reduce(float v, float* red) {
    int t = threadIdx.x;  // 256 threads
    red[t] = v; __syncthreads();
    #pragma unroll
    for (int o = 128; o > 0; o >>= 1) {
        if (t < o) red[t] = MAXRED ? fmaxf(red[t], red[t + o]) : (red[t] + red[t + o]);
        __syncthreads();
    }
    float r = red[0];
    __syncthreads();
    return r;
}

// ---------------- tiny kernels ----------------
__global__ void copy_kernel(const float* __restrict__ in, float* __restrict__ out, int n) {
    int i = blockIdx.x * 256 + threadIdx.x;
    if (i < n) out[i] = in[i];
}

__global__ void wsplit_kernel(const float* __restrict__ w, u16* __restrict__ h,
                              u16* __restrict__ l, int n) {
    for (int i = blockIdx.x * 256 + threadIdx.x; i < n; i += gridDim.x * 256) {
        u16 hh, ll; splitw(w[i], hh, ll);
        h[i] = hh; l[i] = ll;
    }
}

__global__ void adapt_kernel(const float* __restrict__ U, const float* __restrict__ V,
                             const float* __restrict__ sigma, float* __restrict__ adapt) {
    __shared__ float red[256];
    __shared__ float vsum[4];
    int t = threadIdx.x;
    for (int r = 0; r < 4; r++) {
        float s = 0.f;
        for (int j = t; j < ND; j += 256) s += V[r * ND + j];
        s = blk_reduce<false>(s, red);
        if (t == 0) vsum[r] = s;
        __syncthreads();
    }
    float sg = sigma[0];
    for (int i = t; i < ND; i += 256) {
        float a = 0.f;
        #pragma unroll
        for (int r = 0; r < 4; r++) a += U[i * 4 + r] * vsum[r];
        adapt[i] = a * sg;
    }
}

// out = [res +] LN(in; g,b) [+ adapt]; SPLIT: write fp16 hi/lo instead of fp32
template<bool ADD_ADAPT, bool RES, bool SPLIT>
__global__ void ln_kernel(const float* __restrict__ in, const float* __restrict__ g,
                          const float* __restrict__ b, const float* __restrict__ adapt,
                          const float* __restrict__ res, float* __restrict__ out,
                          u16* __restrict__ oh, u16* __restrict__ ol) {
    __shared__ float red[256];
    int row = blockIdx.x, t = threadIdx.x;
    const float* rin = in + (size_t)row * ND;
    float v[4];
    #pragma unroll
    for (int i = 0; i < 4; i++) v[i] = rin[t + i * 256];
    float s = v[0] + v[1] + v[2] + v[3];
    float mean = blk_reduce<false>(s, red) * (1.0f / ND);
    float sq = 0.f;
    #pragma unroll
    for (int i = 0; i < 4; i++) { float d = v[i] - mean; sq += d * d; }
    float var = blk_reduce<false>(sq, red) * (1.0f / ND);
    float inv = rsqrtf(var + LN_EPS);
    #pragma unroll
    for (int i = 0; i < 4; i++) {
        int c = t + i * 256;
        float o = (v[i] - mean) * inv * g[c] + b[c];
        if (ADD_ADAPT) o += adapt[c];
        if (RES)       o += res[(size_t)row * ND + c];
        size_t idx = (size_t)row * ND + c;
        if (SPLIT) { u16 hh, ll; splitw(o, hh, ll); oh[idx] = hh; ol[idx] = ll; }
        else out[idx] = o;
    }
}

// diff = softmax(s1) - softmax(s2), written as split fp16
__global__ void softmax_diff_kernel(const float* __restrict__ s1, const float* __restrict__ s2,
                                    u16* __restrict__ dh, u16* __restrict__ dl) {
    __shared__ float red[256];
    size_t row = blockIdx.x;
    const float* r1 = s1 + row * NS;
    const float* r2 = s2 + row * NS;
    int t = threadIdx.x;
    float v1[4], v2[4];
    #pragma unroll
    for (int i = 0; i < 4; i++) { v1[i] = r1[t + i * 256]; v2[i] = r2[t + i * 256]; }
    float m1 = fmaxf(fmaxf(v1[0], v1[1]), fmaxf(v1[2], v1[3]));
    float m2 = fmaxf(fmaxf(v2[0], v2[1]), fmaxf(v2[2], v2[3]));
    m1 = blk_reduce<true>(m1, red);
    m2 = blk_reduce<true>(m2, red);
    float e1 = 0.f, e2 = 0.f;
    #pragma unroll
    for (int i = 0; i < 4; i++) {
        v1[i] = __expf(v1[i] - m1); e1 += v1[i];
        v2[i] = __expf(v2[i] - m2); e2 += v2[i];
    }
    e1 = blk_reduce<false>(e1, red);
    e2 = blk_reduce<false>(e2, red);
    float i1 = 1.0f / e1, i2 = 1.0f / e2;
    #pragma unroll
    for (int i = 0; i < 4; i++) {
        float d = v1[i] * i1 - v2[i] * i2;
        u16 hh, ll; splitw(d, hh, ll);
        dh[row * NS + t + i * 256] = hh;
        dl[row * NS + t + i * 256] = ll;
    }
}

// vavg[z][k][d] = 0.5*(v1 + v2), from split qkv, written split
__global__ void vavg_kernel(const u16* __restrict__ q1h, const u16* __restrict__ q1l,
                            const u16* __restrict__ q2h, const u16* __restrict__ q2l,
                            u16* __restrict__ oh, u16* __restrict__ ol) {
    int i = blockIdx.x * 256 + threadIdx.x;  // 32*NS*64
    int d = i & 63;
    int k = (i >> 6) & (NS - 1);
    int z = i >> 16;
    int b = z >> 4, h = z & 15;
    size_t src = ((size_t)(b * NS + k)) * 3072 + 2048 + h * 64 + d;
    float v = 0.5f * (joinw(q1h[src], q1l[src]) + joinw(q2h[src], q2l[src]));
    u16 hh, ll; splitw(v, hh, ll);
    oh[i] = hh; ol[i] = ll;
}

// ---------------- split-fp16 tensor-core GEMM, cp.async 2-stage pipeline ----
// C = alpha * A @ op(B) (+bias)(+res)(gelu); inputs are pre-split fp16 hi/lo.
// OUTM: 0 = fp32 to Cf, 1 = split fp16 to Chi/Clo.
// BM=128, BK=32. 256 threads, 2 CTAs/SM.
#define OUT_F32 0
#define OUT_SPLIT 1

template<int BN, bool TRANSB, bool GELU, bool RES, int OUTM>
__global__ void __launch_bounds__(256, 2) mma_gemm(
    const u16* __restrict__ Ahg, const u16* __restrict__ Alg, int lda, long long aO, long long aI,
    const u16* __restrict__ Bhg, const u16* __restrict__ Blg, int ldb, long long bO, long long bI,
    const float* __restrict__ bias, const float* __restrict__ res,
    float* __restrict__ Cf, u16* __restrict__ Chi, u16* __restrict__ Clo,
    int ldc, long long cO, long long cI, int K, float alpha)
{
    constexpr int AP = 40;                           // A smem row stride (halves)
    constexpr int ASZ = 128 * AP;
    constexpr int BROWS = TRANSB ? BN : 32;
    constexpr int BP = TRANSB ? 40 : (BN + 8);
    constexpr int BSZ = BROWS * BP;
    constexpr int STG = 2 * ASZ + 2 * BSZ;           // halves per stage
    extern __shared__ u16 sm[];

    const int t = threadIdx.x;
    const int w = t >> 5, lane = t & 31;
    const int g = lane >> 2, th = lane & 3;
    const int m0 = blockIdx.y * 128, n0 = blockIdx.x * BN;
    const int z = blockIdx.z;
    const long long offA = (long long)(z >> 4) * aO + (long long)(z & 15) * aI;
    const long long offB = (long long)(z >> 4) * bO + (long long)(z & 15) * bI;
    const long long offC = (long long)(z >> 4) * cO + (long long)(z & 15) * cI;
    const u16* Ah_g = Ahg + offA;
    const u16* Al_g = Alg + offA;
    const u16* Bh_g = Bhg + offB;
    const u16* Bl_g = Blg + offB;

    constexpr int MFRAG = (BN == 128) ? 4 : 2;
    const int wm = (BN == 128) ? ((w >> 2) * 64) : ((w >> 1) * 32);
    const int wn = (BN == 128) ? ((w & 3) * 32) : ((w & 1) * 32);

    const int lrow = (lane & 7) + ((lane & 8) ? 8 : 0);
    const int lcol = (lane & 16) ? 8 : 0;
    const uint32_t smbase = smem_u32(sm);

    float acc[MFRAG][4][4] = {};

    auto issue = [&](int kt, int s) {
        const uint32_t ah = smbase + (uint32_t)(s * STG) * 2;
        const uint32_t al = ah + ASZ * 2;
        const uint32_t bh = al + ASZ * 2;
        const uint32_t bl = bh + BSZ * 2;
        // A tile: 128 rows x 32 halves
        #pragma unroll
        for (int c = t; c < 512; c += 256) {
            int row = c >> 2, k8 = (c & 3) * 8;
            size_t gidx = (size_t)(m0 + row) * lda + kt + k8;
            uint32_t doff = (uint32_t)(row * AP + k8) * 2;
            cpa16(ah + doff, Ah_g + gidx);
            cpa16(al + doff, Al_g + gidx);
        }
        if (TRANSB) {
            // B tile: BN rows x 32 halves
            #pragma unroll
            for (int c = t; c < BN * 4; c += 256) {
                int row = c >> 2, k8 = (c & 3) * 8;
                size_t gidx = (size_t)(n0 + row) * ldb + kt + k8;
                uint32_t doff = (uint32_t)(row * BP + k8) * 2;
                cpa16(bh + doff, Bh_g + gidx);
                cpa16(bl + doff, Bl_g + gidx);
            }
        } else {
            // B tile: 32 rows x BN halves
            constexpr int CPR = BN / 8;
            #pragma unroll
            for (int c = t; c < 32 * CPR; c += 256) {
                int row = c / CPR, n8 = (c % CPR) * 8;
                size_t gidx = (size_t)(kt + row) * ldb + n0 + n8;
                uint32_t doff = (uint32_t)(row * BP + n8) * 2;
                cpa16(bh + doff, Bh_g + gidx);
                cpa16(bl + doff, Bl_g + gidx);
            }
        }
    };

    const int tiles = K >> 5;
    issue(0, 0);
    cpacommit();

    for (int i = 0; i < tiles; i++) {
        if (i + 1 < tiles) { issue((i + 1) << 5, (i + 1) & 1); cpacommit(); cpawait<1>(); }
        else cpawait<0>();
        __syncthreads();

        const int s = i & 1;
        const u16* Ah_s = sm + s * STG;
        const u16* Al_s = Ah_s + ASZ;
        const u16* Bh_s = Al_s + ASZ;
        const u16* Bl_s = Bh_s + BSZ;
        const uint32_t bh_base = smbase + (uint32_t)(s * STG + 2 * ASZ) * 2;
        const uint32_t bl_base = bh_base + BSZ * 2;

        #pragma unroll
        for (int ks = 0; ks < 2; ks++) {
            int ko = ks * 16;
            uint32_t bhf[4][2], blf[4][2];
            if (TRANSB) {
                #pragma unroll
                for (int ni = 0; ni < 4; ni++) {
                    int n = wn + ni * 8 + g;
                    bhf[ni][0] = *(const uint32_t*)&Bh_s[n * BP + ko + 2 * th];
                    bhf[ni][1] = *(const uint32_t*)&Bh_s[n * BP + ko + 8 + 2 * th];
                    blf[ni][0] = *(const uint32_t*)&Bl_s[n * BP + ko + 2 * th];
                    blf[ni][1] = *(const uint32_t*)&Bl_s[n * BP + ko + 8 + 2 * th];
                }
            } else {
                #pragma unroll
                for (int pr = 0; pr < 2; pr++) {
                    uint32_t off = (uint32_t)(((ko + lrow) * BP + wn + pr * 16 + lcol) * 2);
                    uint32_t r[4];
                    ldsm4t(r, bh_base + off);
                    bhf[pr*2][0] = r[0]; bhf[pr*2][1] = r[1]; bhf[pr*2+1][0] = r[2]; bhf[pr*2+1][1] = r[3];
                    ldsm4t(r, bl_base + off);
                    blf[pr*2][0] = r[0]; blf[pr*2][1] = r[1]; blf[pr*2+1][0] = r[2]; blf[pr*2+1][1] = r[3];
                }
            }
            uint32_t af[MFRAG][4];
            #pragma unroll
            for (int mi = 0; mi < MFRAG; mi++) {
                int mr = wm + mi * 16 + g;
                af[mi][0] = *(const uint32_t*)&Ah_s[(mr    ) * AP + ko + 2 * th];
                af[mi][1] = *(const uint32_t*)&Ah_s[(mr + 8) * AP + ko + 2 * th];
                af[mi][2] = *(const uint32_t*)&Ah_s[(mr    ) * AP + ko + 8 + 2 * th];
                af[mi][3] = *(const uint32_t*)&Ah_s[(mr + 8) * AP + ko + 8 + 2 * th];
            }
            #pragma unroll
            for (int mi = 0; mi < MFRAG; mi++)
                #pragma unroll
                for (int ni = 0; ni < 4; ni++) {
                    mma16(acc[mi][ni], af[mi], bhf[ni]);
                    mma16(acc[mi][ni], af[mi], blf[ni]);
                }
            #pragma unroll
            for (int mi = 0; mi < MFRAG; mi++) {
                int mr = wm + mi * 16 + g;
                af[mi][0] = *(const uint32_t*)&Al_s[(mr    ) * AP + ko + 2 * th];
                af[mi][1] = *(const uint32_t*)&Al_s[(mr + 8) * AP + ko + 2 * th];
                af[mi][2] = *(const uint32_t*)&Al_s[(mr    ) * AP + ko + 8 + 2 * th];
                af[mi][3] = *(const uint32_t*)&Al_s[(mr + 8) * AP + ko + 8 + 2 * th];
            }
            #pragma unroll
            for (int mi = 0; mi < MFRAG; mi++)
                #pragma unroll
                for (int ni = 0; ni < 4; ni++)
                    mma16(acc[mi][ni], af[mi], bhf[ni]);
        }
        __syncthreads();
    }

    // ---- epilogue ----
    #pragma unroll
    for (int mi = 0; mi < MFRAG; mi++) {
        #pragma unroll
        for (int ni = 0; ni < 4; ni++) {
            int col = n0 + wn + ni * 8 + th * 2;
            #pragma unroll
            for (int half = 0; half < 2; half++) {
                int row = m0 + wm + mi * 16 + g + half * 8;
                float v0 = acc[mi][ni][half * 2 + 0] * alpha;
                float v1 = acc[mi][ni][half * 2 + 1] * alpha;
                if (bias) { v0 += bias[col]; v1 += bias[col + 1]; }
                if (RES) {
                    v0 += res[(size_t)row * ldc + col];
                    v1 += res[(size_t)row * ldc + col + 1];
                }
                if (GELU) {
                    v0 = 0.5f * v0 * (1.0f + erff(v0 * 0.70710678118654752f));
                    v1 = 0.5f * v1 * (1.0f + erff(v1 * 0.70710678118654752f));
                }
                size_t idx = offC + (size_t)row * ldc + col;
                if (OUTM == OUT_SPLIT) {
                    u16 h0, l0, h1, l1;
                    splitw(v0, h0, l0); splitw(v1, h1, l1);
                    *(uint32_t*)&Chi[idx] = (uint32_t)h0 | ((uint32_t)h1 << 16);
                    *(uint32_t*)&Clo[idx] = (uint32_t)l0 | ((uint32_t)l1 << 16);
                } else {
                    *(float2*)&Cf[idx] = make_float2(v0, v1);
                }
            }
        }
    }
}

// ---------------- host orchestration ----------------
extern "C" void kernel_launch(void* const* d_in, const int* in_sizes, int n_in,
                              void* d_out, int out_size) {
    (void)in_sizes; (void)n_in; (void)out_size;
    const float* x     = (const float*)d_in[0];
    const float* sigma = (const float*)d_in[1];
    const float* U     = (const float*)d_in[2];
    const float* V     = (const float*)d_in[3];
    const float* Wqkv1 = (const float*)d_in[4];
    const float* Wqkv2 = (const float*)d_in[5];
    const float* Wp1   = (const float*)d_in[6];
    const float* bp1   = (const float*)d_in[7];
    const float* Wp2   = (const float*)d_in[8];
    const float* bp2   = (const float*)d_in[9];
    const float* Wo    = (const float*)d_in[10];
    const float* bo    = (const float*)d_in[11];
    const float* gO    = (const float*)d_in[12];
    const float* bO    = (const float*)d_in[13];
    const float* g1    = (const float*)d_in[14];
    const float* b1    = (const float*)d_in[15];
    const float* g2    = (const float*)d_in[16];
    const float* b2    = (const float*)d_in[17];
    const float* Wm1   = (const float*)d_in[18];
    const float* bm1   = (const float*)d_in[19];
    const float* Wm2   = (const float*)d_in[20];
    const float* bm2   = (const float*)d_in[21];
    const float* gf    = (const float*)d_in[22];
    const float* bf    = (const float*)d_in[23];

    float *px, *ptmp, *ps1, *ps2, *pad;
    u16 *wh, *wl, *hh, *hl, *x1h, *x1l, *x2h, *x2l, *q1h, *q1l, *q2h, *q2l;
    u16 *dh, *dl, *vah, *val, *ph_, *pl_, *mh, *ml;
    cudaGetSymbolAddress((void**)&px,   g_x);
    cudaGetSymbolAddress((void**)&ptmp, g_tmp);
    cudaGetSymbolAddress((void**)&ps1,  g_s1);
    cudaGetSymbolAddress((void**)&ps2,  g_s2);
    cudaGetSymbolAddress((void**)&pad,  g_adapt);
    cudaGetSymbolAddress((void**)&wh,   g_wh);
    cudaGetSymbolAddress((void**)&wl,   g_wl);
    cudaGetSymbolAddress((void**)&hh,   g_hh);
    cudaGetSymbolAddress((void**)&hl,   g_hl);
    cudaGetSymbolAddress((void**)&x1h,  g_x1h);
    cudaGetSymbolAddress((void**)&x1l,  g_x1l);
    cudaGetSymbolAddress((void**)&x2h,  g_x2h);
    cudaGetSymbolAddress((void**)&x2l,  g_x2l);
    cudaGetSymbolAddress((void**)&q1h,  g_q1h);
    cudaGetSymbolAddress((void**)&q1l,  g_q1l);
    cudaGetSymbolAddress((void**)&q2h,  g_q2h);
    cudaGetSymbolAddress((void**)&q2l,  g_q2l);
    cudaGetSymbolAddress((void**)&dh,   g_dh);
    cudaGetSymbolAddress((void**)&dl,   g_dl);
    cudaGetSymbolAddress((void**)&vah,  g_vah);
    cudaGetSymbolAddress((void**)&val,  g_val);
    cudaGetSymbolAddress((void**)&ph_,  g_ph);
    cudaGetSymbolAddress((void**)&pl_,  g_pl);
    cudaGetSymbolAddress((void**)&mh,   g_mh);
    cudaGetSymbolAddress((void**)&ml,   g_ml);

    // dynamic smem opt-in (bytes = 2 stages * STG halves * 2B)
    const int SM_W   = 2 * (2*128*40 + 2*32*136) * 2;   // 75776  (BN=128, weights)
    const int SM_SC  = 2 * (2*128*40 + 2*128*40) * 2;   // 81920  (TRANSB)
    const int SM_PV  = 2 * (2*128*40 + 2*32*72)  * 2;   // 59392  (BN=64)
    cudaFuncSetAttribute((const void*)mma_gemm<128,false,false,false,OUT_SPLIT>, cudaFuncAttributeMaxDynamicSharedMemorySize, SM_W);
    cudaFuncSetAttribute((const void*)mma_gemm<128,false,false,false,OUT_F32>,   cudaFuncAttributeMaxDynamicSharedMemorySize, SM_W);
    cudaFuncSetAttribute((const void*)mma_gemm<128,false,true, false,OUT_SPLIT>, cudaFuncAttributeMaxDynamicSharedMemorySize, SM_W);
    cudaFuncSetAttribute((const void*)mma_gemm<128,false,false,true, OUT_F32>,   cudaFuncAttributeMaxDynamicSharedMemorySize, SM_W);
    cudaFuncSetAttribute((const void*)mma_gemm<128,true, false,false,OUT_F32>,   cudaFuncAttributeMaxDynamicSharedMemorySize, SM_SC);
    cudaFuncSetAttribute((const void*)mma_gemm<64, false,false,false,OUT_SPLIT>, cudaFuncAttributeMaxDynamicSharedMemorySize, SM_PV);

    copy_kernel<<<NTOK * ND / 256, 256>>>(x, px, NTOK * ND);

    // pre-split all weights
    const size_t WL = 16777216;  // per-layer half offset
    for (int l = 0; l < NL; l++) {
        size_t base = (size_t)l * WL;
        wsplit_kernel<<<2048, 256>>>(Wp1   + (size_t)l*512*ND,    wh+base+0,       wl+base+0,       512*ND);
        wsplit_kernel<<<2048, 256>>>(Wp2   + (size_t)l*512*ND,    wh+base+524288,  wl+base+524288,  512*ND);
        wsplit_kernel<<<4096, 256>>>(Wqkv1 + (size_t)l*ND*3*ND,   wh+base+1048576, wl+base+1048576, ND*3*ND);
        wsplit_kernel<<<4096, 256>>>(Wqkv2 + (size_t)l*ND*3*ND,   wh+base+4194304, wl+base+4194304, ND*3*ND);
        wsplit_kernel<<<2048, 256>>>(Wo    + (size_t)l*ND*ND,     wh+base+7340032, wl+base+7340032, ND*ND);
        wsplit_kernel<<<4096, 256>>>(Wm1   + (size_t)l*ND*4*ND,   wh+base+8388608, wl+base+8388608, ND*4*ND);
        wsplit_kernel<<<4096, 256>>>(Wm2   + (size_t)l*4*ND*ND,   wh+base+12582912,wl+base+12582912,4*ND*ND);
    }

    const long long ZA = (long long)NS * 3072;   // qkv batch stride (b)
    const long long ZS = (long long)NS * NS;     // scores batch (z)
    const long long ZV = (long long)NS * NDH;    // vavg batch (z)

    for (int l = 0; l < NL; l++) {
        size_t base = (size_t)l * WL;
        adapt_kernel<<<1, 256>>>(U + (size_t)l * ND * 4, V + (size_t)l * 4 * ND, sigma + l, pad);
        ln_kernel<true, false, true><<<NTOK, 256>>>(px, g1 + l*ND, b1 + l*ND, pad, nullptr, nullptr, hh, hl);

        // x1p = a[:,:512] @ Wp1 + bp1 ; x2p = a[:,512:] @ Wp2 + bp2  (split out)
        mma_gemm<128,false,false,false,OUT_SPLIT><<<dim3(8,16), 256, SM_W>>>(
            hh, hl, ND, 0, 0, wh+base, wl+base, ND, 0, 0,
            bp1 + l*ND, nullptr, nullptr, x1h, x1l, ND, 0, 0, 512, 1.0f);
        mma_gemm<128,false,false,false,OUT_SPLIT><<<dim3(8,16), 256, SM_W>>>(
            hh+512, hl+512, ND, 0, 0, wh+base+524288, wl+base+524288, ND, 0, 0,
            bp2 + l*ND, nullptr, nullptr, x2h, x2l, ND, 0, 0, 512, 1.0f);

        // qkv = x?p @ Wqkv?  (split out)
        mma_gemm<128,false,false,false,OUT_SPLIT><<<dim3(24,16), 256, SM_W>>>(
            x1h, x1l, ND, 0, 0, wh+base+1048576, wl+base+1048576, 3*ND, 0, 0,
            nullptr, nullptr, nullptr, q1h, q1l, 3*ND, 0, 0, ND, 1.0f);
        mma_gemm<128,false,false,false,OUT_SPLIT><<<dim3(24,16), 256, SM_W>>>(
            x2h, x2l, ND, 0, 0, wh+base+4194304, wl+base+4194304, 3*ND, 0, 0,
            nullptr, nullptr, nullptr, q2h, q2l, 3*ND, 0, 0, ND, 1.0f);

        // scores (fp32 out)
        mma_gemm<128,true,false,false,OUT_F32><<<dim3(8,8,32), 256, SM_SC>>>(
            q1h, q1l, 3072, ZA, 64, q1h+ND, q1l+ND, 3072, ZA, 64,
            nullptr, nullptr, ps1, nullptr, nullptr, NS, 16*ZS, ZS, NDH, ATT_SCALE);
        mma_gemm<128,true,false,false,OUT_F32><<<dim3(8,8,32), 256, SM_SC>>>(
            q2h, q2l, 3072, ZA, 64, q2h+ND, q2l+ND, 3072, ZA, 64,
            nullptr, nullptr, ps2, nullptr, nullptr, NS, 16*ZS, ZS, NDH, ATT_SCALE);

        softmax_diff_kernel<<<NB*NH*NS, 256>>>(ps1, ps2, dh, dl);
        vavg_kernel<<<32*NS*NDH/256, 256>>>(q1h, q1l, q2h, q2l, vah, val);

        // PV (split out, written as [b,s,h*64+d])
        mma_gemm<64,false,false,false,OUT_SPLIT><<<dim3(1,8,32), 256, SM_PV>>>(
            dh, dl, NS, 16*ZS, ZS, vah, val, NDH, 16*ZV, ZV,
            nullptr, nullptr, nullptr, ph_, pl_, ND, (long long)NS*ND, 64, NS, 1.0f);

        // out proj (fp32) + post-LN + residual
        mma_gemm<128,false,false,false,OUT_F32><<<dim3(8,16), 256, SM_W>>>(
            ph_, pl_, ND, 0, 0, wh+base+7340032, wl+base+7340032, ND, 0, 0,
            bo + l*ND, nullptr, ptmp, nullptr, nullptr, ND, 0, 0, ND, 1.0f);
        ln_kernel<false, true, false><<<NTOK, 256>>>(ptmp, gO + l*ND, bO + l*ND, nullptr, px, px, nullptr, nullptr);

        // MLP
        ln_kernel<false, false, true><<<NTOK, 256>>>(px, g2 + l*ND, b2 + l*ND, nullptr, nullptr, nullptr, hh, hl);
        mma_gemm<128,false,true,false,OUT_SPLIT><<<dim3(32,16), 256, SM_W>>>(
            hh, hl, ND, 0, 0, wh+base+8388608, wl+base+8388608, 4*ND, 0, 0,
            bm1 + (size_t)l*4*ND, nullptr, nullptr, mh, ml, 4*ND, 0, 0, ND, 1.0f);
        mma_gemm<128,false,false,true,OUT_F32><<<dim3(8,16), 256, SM_W>>>(
            mh, ml, 4*ND, 0, 0, wh+base+12582912, wl+base+12582912, ND, 0, 0,
            bm2 + l*ND, px, px, nullptr, nullptr, ND, 0, 0, 4*ND, 1.0f);
    }

    ln_kernel<false, false, false><<<NTOK, 256>>>(px, gf, bf, nullptr, nullptr, (float*)d_out, nullptr, nullptr);
}

// round 7
// speedup vs baseline: 2.9518x; 1.0258x over previous
#include <cuda_runtime.h>
#include <cuda_fp16.h>
#include <math.h>
#include <stdint.h>

#define NL 4
#define NB 2
#define NS 1024
#define ND 1024
#define NH 16
#define NDH 64
#define NTOK (NB*NS)        // 2048
#define ATT_SCALE 0.125f
#define LN_EPS 1e-5f

typedef unsigned short u16;

// ---------------- scratch (static device globals: alloc-free) ----------------
__device__ float g_x    [NTOK*ND];
__device__ float g_tmp  [NTOK*ND];
__device__ float g_s1   [(size_t)NB*NH*NS*NS];   // scores fp32 (134 MB)
__device__ float g_s2   [(size_t)NB*NH*NS*NS];
__device__ float g_adapt[ND];

// split fp16 weights, grouped by TYPE (contiguous across layers)
#define WTOT 67108864ULL
#define OFF_P1 0ULL
#define OFF_P2 2097152ULL
#define OFF_Q1 4194304ULL
#define OFF_Q2 16777216ULL
#define OFF_O  29360128ULL
#define OFF_M1 33554432ULL
#define OFF_M2 50331648ULL
__device__ u16 g_wh [WTOT];
__device__ u16 g_wl [WTOT];
__device__ u16 g_hh [NTOK*ND],      g_hl [NTOK*ND];       // LN out
__device__ u16 g_x1h[NTOK*ND],      g_x1l[NTOK*ND];
__device__ u16 g_x2h[NTOK*ND],      g_x2l[NTOK*ND];
__device__ u16 g_q1h[NTOK*3*ND],    g_q1l[NTOK*3*ND];
__device__ u16 g_q2h[NTOK*3*ND],    g_q2l[NTOK*3*ND];
__device__ u16 g_dh [(size_t)32*NS*NS], g_dl[(size_t)32*NS*NS]; // softmax diff
__device__ u16 g_vah[32*NS*NDH],    g_val[32*NS*NDH];
__device__ u16 g_ph [NTOK*ND],      g_pl [NTOK*ND];       // attn out
__device__ u16 g_mh [NTOK*4*ND],    g_ml [NTOK*4*ND];     // gelu out

// ---------------- helpers ----------------
__device__ __forceinline__ uint32_t smem_u32(const void* p) {
    uint32_t a;
    asm("{ .reg .u64 t; cvta.to.shared.u64 t, %1; cvt.u32.u64 %0, t; }" : "=r"(a) : "l"(p));
    return a;
}
__device__ __forceinline__ void splitw(float v, u16& h, u16& l) {
    __half hh = __float2half_rn(v);
    h = __half_as_ushort(hh);
    l = __half_as_ushort(__float2half_rn(v - __half2float(hh)));
}
__device__ __forceinline__ float joinw(u16 h, u16 l) {
    return __half2float(__ushort_as_half(h)) + __half2float(__ushort_as_half(l));
}
__device__ __forceinline__ void mma16(float* c, const uint32_t* a, const uint32_t* b) {
    asm volatile(
        "mma.sync.aligned.m16n8k16.row.col.f32.f16.f16.f32 "
        "{%0,%1,%2,%3},{%4,%5,%6,%7},{%8,%9},{%0,%1,%2,%3};\n"
        : "+f"(c[0]), "+f"(c[1]), "+f"(c[2]), "+f"(c[3])
        : "r"(a[0]), "r"(a[1]), "r"(a[2]), "r"(a[3]), "r"(b[0]), "r"(b[1]));
}
__device__ __forceinline__ void ldsm4t(uint32_t* r, uint32_t addr) {
    asm volatile("ldmatrix.sync.aligned.m8n8.x4.trans.shared.b16 {%0,%1,%2,%3}, [%4];"
        : "=r"(r[0]), "=r"(r[1]), "=r"(r[2]), "=r"(r[3]) : "r"(addr));
}
__device__ __forceinline__ void cpa16(uint32_t dst, const void* src) {
    asm volatile("cp.async.cg.shared.global [%0], [%1], 16;" :: "r"(dst), "l"(src));
}
__device__ __forceinline__ void cpacommit() { asm volatile("cp.async.commit_group;"); }
template<int N> __device__ __forceinline__ void cpawait() {
    asm volatile("cp.async.wait_group %0;" :: "n"(N));
}

template<bool MAXRED>
__device__ __forceinline__ float blk_reduce(float v, float* red) {
    int t = threadIdx.x;  // 256 threads
    red[t] = v; __syncthreads();
    #pragma unroll
    for (int o = 128; o > 0; o >>= 1) {
        if (t < o) red[t] = MAXRED ? fmaxf(red[t], red[t + o]) : (red[t] + red[t + o]);
        __syncthreads();
    }
    float r = red[0];
    __syncthreads();
    return r;
}

// ---------------- tiny kernels ----------------
__global__ void copy_kernel(const float* __restrict__ in, float* __restrict__ out, int n) {
    int i = blockIdx.x * 256 + threadIdx.x;
    if (i < n) out[i] = in[i];
}

// vectorized split (n multiple of 4)
__global__ void wsplit_kernel(const float* __restrict__ w, u16* __restrict__ h,
                              u16* __restrict__ l, size_t n) {
    for (size_t i = ((size_t)blockIdx.x * 256 + threadIdx.x) * 4; i < n;
         i += (size_t)gridDim.x * 1024) {
        float4 v = *(const float4*)(w + i);
        u16 h0,l0,h1,l1,h2,l2,h3,l3;
        splitw(v.x,h0,l0); splitw(v.y,h1,l1); splitw(v.z,h2,l2); splitw(v.w,h3,l3);
        *(uint2*)(h + i) = make_uint2((uint32_t)h0 | ((uint32_t)h1<<16),
                                      (uint32_t)h2 | ((uint32_t)h3<<16));
        *(uint2*)(l + i) = make_uint2((uint32_t)l0 | ((uint32_t)l1<<16),
                                      (uint32_t)l2 | ((uint32_t)l3<<16));
    }
}

__global__ void adapt_kernel(const float* __restrict__ U, const float* __restrict__ V,
                             const float* __restrict__ sigma, float* __restrict__ adapt) {
    __shared__ float red[256];
    __shared__ float vsum[4];
    int t = threadIdx.x;
    for (int r = 0; r < 4; r++) {
        float s = 0.f;
        for (int j = t; j < ND; j += 256) s += V[r * ND + j];
        s = blk_reduce<false>(s, red);
        if (t == 0) vsum[r] = s;
        __syncthreads();
    }
    float sg = sigma[0];
    for (int i = t; i < ND; i += 256) {
        float a = 0.f;
        #pragma unroll
        for (int r = 0; r < 4; r++) a += U[i * 4 + r] * vsum[r];
        adapt[i] = a * sg;
    }
}

template<bool ADD_ADAPT, bool RES, bool SPLIT>
__global__ void ln_kernel(const float* __restrict__ in, const float* __restrict__ g,
                          const float* __restrict__ b, const float* __restrict__ adapt,
                          const float* __restrict__ res, float* __restrict__ out,
                          u16* __restrict__ oh, u16* __restrict__ ol) {
    __shared__ float red[256];
    int row = blockIdx.x, t = threadIdx.x;
    const float* rin = in + (size_t)row * ND;
    float v[4];
    #pragma unroll
    for (int i = 0; i < 4; i++) v[i] = rin[t + i * 256];
    float s = v[0] + v[1] + v[2] + v[3];
    float mean = blk_reduce<false>(s, red) * (1.0f / ND);
    float sq = 0.f;
    #pragma unroll
    for (int i = 0; i < 4; i++) { float d = v[i] - mean; sq += d * d; }
    float var = blk_reduce<false>(sq, red) * (1.0f / ND);
    float inv = rsqrtf(var + LN_EPS);
    #pragma unroll
    for (int i = 0; i < 4; i++) {
        int c = t + i * 256;
        float o = (v[i] - mean) * inv * g[c] + b[c];
        if (ADD_ADAPT) o += adapt[c];
        if (RES)       o += res[(size_t)row * ND + c];
        size_t idx = (size_t)row * ND + c;
        if (SPLIT) { u16 hh, ll; splitw(o, hh, ll); oh[idx] = hh; ol[idx] = ll; }
        else out[idx] = o;
    }
}

__global__ void softmax_diff_kernel(const float* __restrict__ s1, const float* __restrict__ s2,
                                    u16* __restrict__ dh, u16* __restrict__ dl) {
    __shared__ float red[256];
    size_t row = blockIdx.x;
    const float* r1 = s1 + row * NS;
    const float* r2 = s2 + row * NS;
    int t = threadIdx.x;
    float v1[4], v2[4];
    #pragma unroll
    for (int i = 0; i < 4; i++) { v1[i] = r1[t + i * 256]; v2[i] = r2[t + i * 256]; }
    float m1 = fmaxf(fmaxf(v1[0], v1[1]), fmaxf(v1[2], v1[3]));
    float m2 = fmaxf(fmaxf(v2[0], v2[1]), fmaxf(v2[2], v2[3]));
    m1 = blk_reduce<true>(m1, red);
    m2 = blk_reduce<true>(m2, red);
    float e1 = 0.f, e2 = 0.f;
    #pragma unroll
    for (int i = 0; i < 4; i++) {
        v1[i] = __expf(v1[i] - m1); e1 += v1[i];
        v2[i] = __expf(v2[i] - m2); e2 += v2[i];
    }
    e1 = blk_reduce<false>(e1, red);
    e2 = blk_reduce<false>(e2, red);
    float i1 = 1.0f / e1, i2 = 1.0f / e2;
    #pragma unroll
    for (int i = 0; i < 4; i++) {
        float d = v1[i] * i1 - v2[i] * i2;
        u16 hh, ll; splitw(d, hh, ll);
        dh[row * NS + t + i * 256] = hh;
        dl[row * NS + t + i * 256] = ll;
    }
}

__global__ void vavg_kernel(const u16* __restrict__ q1h, const u16* __restrict__ q1l,
                            const u16* __restrict__ q2h, const u16* __restrict__ q2l,
                            u16* __restrict__ oh, u16* __restrict__ ol) {
    int i = blockIdx.x * 256 + threadIdx.x;  // 32*NS*64
    int d = i & 63;
    int k = (i >> 6) & (NS - 1);
    int z = i >> 16;
    int b = z >> 4, h = z & 15;
    size_t src = ((size_t)(b * NS + k)) * 3072 + 2048 + h * 64 + d;
    float v = 0.5f * (joinw(q1h[src], q1l[src]) + joinw(q2h[src], q2l[src]));
    u16 hh, ll; splitw(v, hh, ll);
    oh[i] = hh; ol[i] = ll;
}

// ---------------- split-fp16 mma.sync GEMM, NSTG-stage cp.async pipeline -----
// C = alpha * A @ op(B) (+bias)(+res)(gelu); inputs pre-split fp16 hi/lo.
// One __syncthreads per K-tile (wait -> sync -> issue next -> compute).
#define OUT_F32 0
#define OUT_SPLIT 1

template<int BN, bool TRANSB, bool GELU, bool RES, int OUTM, int NSTG>
__global__ void __launch_bounds__(256, 2) mma_gemm(
    const u16* __restrict__ Ahg, const u16* __restrict__ Alg, int lda, long long aO, long long aI,
    const u16* __restrict__ Bhg, const u16* __restrict__ Blg, int ldb, long long bO, long long bI,
    const float* __restrict__ bias, const float* __restrict__ res,
    float* __restrict__ Cf, u16* __restrict__ Chi, u16* __restrict__ Clo,
    int ldc, long long cO, long long cI, int K, float alpha)
{
    constexpr int AP = 40;
    constexpr int ASZ = 128 * AP;
    constexpr int BROWS = TRANSB ? BN : 32;
    constexpr int BP = TRANSB ? 40 : (BN + 8);
    constexpr int BSZ = BROWS * BP;
    constexpr int STG = 2 * ASZ + 2 * BSZ;
    extern __shared__ u16 sm[];

    const int t = threadIdx.x;
    const int w = t >> 5, lane = t & 31;
    const int g = lane >> 2, th = lane & 3;
    const int m0 = blockIdx.y * 128, n0 = blockIdx.x * BN;
    const int z = blockIdx.z;
    const long long offA = (long long)(z >> 4) * aO + (long long)(z & 15) * aI;
    const long long offB = (long long)(z >> 4) * bO + (long long)(z & 15) * bI;
    const long long offC = (long long)(z >> 4) * cO + (long long)(z & 15) * cI;
    const u16* Ah_g = Ahg + offA;
    const u16* Al_g = Alg + offA;
    const u16* Bh_g = Bhg + offB;
    const u16* Bl_g = Blg + offB;

    constexpr int MFRAG = (BN == 128) ? 4 : 2;
    const int wm = (BN == 128) ? ((w >> 2) * 64) : ((w >> 1) * 32);
    const int wn = (BN == 128) ? ((w & 3) * 32) : ((w & 1) * 32);

    const int lrow = (lane & 7) + ((lane & 8) ? 8 : 0);
    const int lcol = (lane & 16) ? 8 : 0;
    const uint32_t smbase = smem_u32(sm);

    float acc[MFRAG][4][4] = {};

    auto issue = [&](int kt, int s) {
        const uint32_t ah = smbase + (uint32_t)(s * STG) * 2;
        const uint32_t al = ah + ASZ * 2;
        const uint32_t bh = al + ASZ * 2;
        const uint32_t bl = bh + BSZ * 2;
        #pragma unroll
        for (int c = t; c < 512; c += 256) {
            int row = c >> 2, k8 = (c & 3) * 8;
            size_t gidx = (size_t)(m0 + row) * lda + kt + k8;
            uint32_t doff = (uint32_t)(row * AP + k8) * 2;
            cpa16(ah + doff, Ah_g + gidx);
            cpa16(al + doff, Al_g + gidx);
        }
        if (TRANSB) {
            #pragma unroll
            for (int c = t; c < BN * 4; c += 256) {
                int row = c >> 2, k8 = (c & 3) * 8;
                size_t gidx = (size_t)(n0 + row) * ldb + kt + k8;
                uint32_t doff = (uint32_t)(row * BP + k8) * 2;
                cpa16(bh + doff, Bh_g + gidx);
                cpa16(bl + doff, Bl_g + gidx);
            }
        } else {
            constexpr int CPR = BN / 8;
            #pragma unroll
            for (int c = t; c < 32 * CPR; c += 256) {
                int row = c / CPR, n8 = (c % CPR) * 8;
                size_t gidx = (size_t)(kt + row) * ldb + n0 + n8;
                uint32_t doff = (uint32_t)(row * BP + n8) * 2;
                cpa16(bh + doff, Bh_g + gidx);
                cpa16(bl + doff, Bl_g + gidx);
            }
        }
        cpacommit();
    };

    const int tiles = K >> 5;
    #pragma unroll
    for (int p = 0; p < NSTG - 1 && p < tiles; p++) issue(p << 5, p % NSTG);

    for (int i = 0; i < tiles; i++) {
        cpawait<NSTG - 2>();
        __syncthreads();
        {
            int nx = i + NSTG - 1;
            if (nx < tiles) issue(nx << 5, nx % NSTG);
        }
        const int s = i % NSTG;
        const u16* Ah_s = sm + s * STG;
        const u16* Al_s = Ah_s + ASZ;
        const u16* Bh_s = Al_s + ASZ;
        const u16* Bl_s = Bh_s + BSZ;
        const uint32_t bh_base = smbase + (uint32_t)(s * STG + 2 * ASZ) * 2;
        const uint32_t bl_base = bh_base + BSZ * 2;

        #pragma unroll
        for (int ks = 0; ks < 2; ks++) {
            int ko = ks * 16;
            uint32_t bhf[4][2], blf[4][2];
            if (TRANSB) {
                #pragma unroll
                for (int ni = 0; ni < 4; ni++) {
                    int n = wn + ni * 8 + g;
                    bhf[ni][0] = *(const uint32_t*)&Bh_s[n * BP + ko + 2 * th];
                    bhf[ni][1] = *(const uint32_t*)&Bh_s[n * BP + ko + 8 + 2 * th];
                    blf[ni][0] = *(const uint32_t*)&Bl_s[n * BP + ko + 2 * th];
                    blf[ni][1] = *(const uint32_t*)&Bl_s[n * BP + ko + 8 + 2 * th];
                }
            } else {
                #pragma unroll
                for (int pr = 0; pr < 2; pr++) {
                    uint32_t off = (uint32_t)(((ko + lrow) * BP + wn + pr * 16 + lcol) * 2);
                    uint32_t r[4];
                    ldsm4t(r, bh_base + off);
                    bhf[pr*2][0] = r[0]; bhf[pr*2][1] = r[1]; bhf[pr*2+1][0] = r[2]; bhf[pr*2+1][1] = r[3];
                    ldsm4t(r, bl_base + off);
                    blf[pr*2][0] = r[0]; blf[pr*2][1] = r[1]; blf[pr*2+1][0] = r[2]; blf[pr*2+1][1] = r[3];
                }
            }
            uint32_t af[MFRAG][4];
            #pragma unroll
            for (int mi = 0; mi < MFRAG; mi++) {
                int mr = wm + mi * 16 + g;
                af[mi][0] = *(const uint32_t*)&Ah_s[(mr    ) * AP + ko + 2 * th];
                af[mi][1] = *(const uint32_t*)&Ah_s[(mr + 8) * AP + ko + 2 * th];
                af[mi][2] = *(const uint32_t*)&Ah_s[(mr    ) * AP + ko + 8 + 2 * th];
                af[mi][3] = *(const uint32_t*)&Ah_s[(mr + 8) * AP + ko + 8 + 2 * th];
            }
            #pragma unroll
            for (int mi = 0; mi < MFRAG; mi++)
                #pragma unroll
                for (int ni = 0; ni < 4; ni++) {
                    mma16(acc[mi][ni], af[mi], bhf[ni]);
                    mma16(acc[mi][ni], af[mi], blf[ni]);
                }
            #pragma unroll
            for (int mi = 0; mi < MFRAG; mi++) {
                int mr = wm + mi * 16 + g;
                af[mi][0] = *(const uint32_t*)&Al_s[(mr    ) * AP + ko + 2 * th];
                af[mi][1] = *(const uint32_t*)&Al_s[(mr + 8) * AP + ko + 2 * th];
                af[mi][2] = *(const uint32_t*)&Al_s[(mr    ) * AP + ko + 8 + 2 * th];
                af[mi][3] = *(const uint32_t*)&Al_s[(mr + 8) * AP + ko + 8 + 2 * th];
            }
            #pragma unroll
            for (int mi = 0; mi < MFRAG; mi++)
                #pragma unroll
                for (int ni = 0; ni < 4; ni++)
                    mma16(acc[mi][ni], af[mi], bhf[ni]);
        }
    }

    // ---- epilogue ----
    #pragma unroll
    for (int mi = 0; mi < MFRAG; mi++) {
        #pragma unroll
        for (int ni = 0; ni < 4; ni++) {
            int col = n0 + wn + ni * 8 + th * 2;
            #pragma unroll
            for (int half = 0; half < 2; half++) {
                int row = m0 + wm + mi * 16 + g + half * 8;
                float v0 = acc[mi][ni][half * 2 + 0] * alpha;
                float v1 = acc[mi][ni][half * 2 + 1] * alpha;
                if (bias) { v0 += bias[col]; v1 += bias[col + 1]; }
                if (RES) {
                    v0 += res[(size_t)row * ldc + col];
                    v1 += res[(size_t)row * ldc + col + 1];
                }
                if (GELU) {
                    v0 = 0.5f * v0 * (1.0f + erff(v0 * 0.70710678118654752f));
                    v1 = 0.5f * v1 * (1.0f + erff(v1 * 0.70710678118654752f));
                }
                size_t idx = offC + (size_t)row * ldc + col;
                if (OUTM == OUT_SPLIT) {
                    u16 h0, l0, h1, l1;
                    splitw(v0, h0, l0); splitw(v1, h1, l1);
                    *(uint32_t*)&Chi[idx] = (uint32_t)h0 | ((uint32_t)h1 << 16);
                    *(uint32_t*)&Clo[idx] = (uint32_t)l0 | ((uint32_t)l1 << 16);
                } else {
                    *(float2*)&Cf[idx] = make_float2(v0, v1);
                }
            }
        }
    }
}

// ---------------- host orchestration ----------------
extern "C" void kernel_launch(void* const* d_in, const int* in_sizes, int n_in,
                              void* d_out, int out_size) {
    (void)in_sizes; (void)n_in; (void)out_size;
    const float* x     = (const float*)d_in[0];
    const float* sigma = (const float*)d_in[1];
    const float* U     = (const float*)d_in[2];
    const float* V     = (const float*)d_in[3];
    const float* Wqkv1 = (const float*)d_in[4];
    const float* Wqkv2 = (const float*)d_in[5];
    const float* Wp1   = (const float*)d_in[6];
    const float* bp1   = (const float*)d_in[7];
    const float* Wp2   = (const float*)d_in[8];
    const float* bp2   = (const float*)d_in[9];
    const float* Wo    = (const float*)d_in[10];
    const float* bo    = (const float*)d_in[11];
    const float* gO    = (const float*)d_in[12];
    const float* bO    = (const float*)d_in[13];
    const float* g1    = (const float*)d_in[14];
    const float* b1    = (const float*)d_in[15];
    const float* g2    = (const float*)d_in[16];
    const float* b2    = (const float*)d_in[17];
    const float* Wm1   = (const float*)d_in[18];
    const float* bm1   = (const float*)d_in[19];
    const float* Wm2   = (const float*)d_in[20];
    const float* bm2   = (const float*)d_in[21];
    const float* gf    = (const float*)d_in[22];
    const float* bf    = (const float*)d_in[23];

    float *px, *ptmp, *ps1, *ps2, *pad;
    u16 *wh, *wl, *hh, *hl, *x1h, *x1l, *x2h, *x2l, *q1h, *q1l, *q2h, *q2l;
    u16 *dh, *dl, *vah, *val, *ph_, *pl_, *mh, *ml;
    cudaGetSymbolAddress((void**)&px,   g_x);
    cudaGetSymbolAddress((void**)&ptmp, g_tmp);
    cudaGetSymbolAddress((void**)&ps1,  g_s1);
    cudaGetSymbolAddress((void**)&ps2,  g_s2);
    cudaGetSymbolAddress((void**)&pad,  g_adapt);
    cudaGetSymbolAddress((void**)&wh,   g_wh);
    cudaGetSymbolAddress((void**)&wl,   g_wl);
    cudaGetSymbolAddress((void**)&hh,   g_hh);
    cudaGetSymbolAddress((void**)&hl,   g_hl);
    cudaGetSymbolAddress((void**)&x1h,  g_x1h);
    cudaGetSymbolAddress((void**)&x1l,  g_x1l);
    cudaGetSymbolAddress((void**)&x2h,  g_x2h);
    cudaGetSymbolAddress((void**)&x2l,  g_x2l);
    cudaGetSymbolAddress((void**)&q1h,  g_q1h);
    cudaGetSymbolAddress((void**)&q1l,  g_q1l);
    cudaGetSymbolAddress((void**)&q2h,  g_q2h);
    cudaGetSymbolAddress((void**)&q2l,  g_q2l);
    cudaGetSymbolAddress((void**)&dh,   g_dh);
    cudaGetSymbolAddress((void**)&dl,   g_dl);
    cudaGetSymbolAddress((void**)&vah,  g_vah);
    cudaGetSymbolAddress((void**)&val,  g_val);
    cudaGetSymbolAddress((void**)&ph_,  g_ph);
    cudaGetSymbolAddress((void**)&pl_,  g_pl);
    cudaGetSymbolAddress((void**)&mh,   g_mh);
    cudaGetSymbolAddress((void**)&ml,   g_ml);

    // dynamic smem sizes (bytes): NSTG * STG halves * 2
    const int SM_B128_S2 = 2 * (2*128*40 + 2*32*136) * 2;   // 75776
    const int SM_B64_S3  = 3 * (2*128*40 + 2*32*72)  * 2;   // 89088
    const int SM_SC_S2   = 2 * (2*128*40 + 2*128*40) * 2;   // 81920
    cudaFuncSetAttribute((const void*)mma_gemm<64, false,false,false,OUT_SPLIT,3>, cudaFuncAttributeMaxDynamicSharedMemorySize, SM_B64_S3);
    cudaFuncSetAttribute((const void*)mma_gemm<64, false,false,false,OUT_F32,  3>, cudaFuncAttributeMaxDynamicSharedMemorySize, SM_B64_S3);
    cudaFuncSetAttribute((const void*)mma_gemm<64, false,false,true, OUT_F32,  3>, cudaFuncAttributeMaxDynamicSharedMemorySize, SM_B64_S3);
    cudaFuncSetAttribute((const void*)mma_gemm<128,false,false,false,OUT_SPLIT,2>, cudaFuncAttributeMaxDynamicSharedMemorySize, SM_B128_S2);
    cudaFuncSetAttribute((const void*)mma_gemm<128,false,true, false,OUT_SPLIT,2>, cudaFuncAttributeMaxDynamicSharedMemorySize, SM_B128_S2);
    cudaFuncSetAttribute((const void*)mma_gemm<128,true, false,false,OUT_F32,  2>, cudaFuncAttributeMaxDynamicSharedMemorySize, SM_SC_S2);

    copy_kernel<<<NTOK * ND / 256, 256>>>(x, px, NTOK * ND);

    // pre-split weights, grouped by type (7 launches)
    wsplit_kernel<<<2048, 256>>>(Wp1,   wh + OFF_P1, wl + OFF_P1, (size_t)NL*512*ND);
    wsplit_kernel<<<2048, 256>>>(Wp2,   wh + OFF_P2, wl + OFF_P2, (size_t)NL*512*ND);
    wsplit_kernel<<<4096, 256>>>(Wqkv1, wh + OFF_Q1, wl + OFF_Q1, (size_t)NL*ND*3*ND);
    wsplit_kernel<<<4096, 256>>>(Wqkv2, wh + OFF_Q2, wl + OFF_Q2, (size_t)NL*ND*3*ND);
    wsplit_kernel<<<2048, 256>>>(Wo,    wh + OFF_O,  wl + OFF_O,  (size_t)NL*ND*ND);
    wsplit_kernel<<<4096, 256>>>(Wm1,   wh + OFF_M1, wl + OFF_M1, (size_t)NL*ND*4*ND);
    wsplit_kernel<<<4096, 256>>>(Wm2,   wh + OFF_M2, wl + OFF_M2, (size_t)NL*4*ND*ND);

    const long long ZA = (long long)NS * 3072;   // qkv batch stride (b)
    const long long ZS = (long long)NS * NS;     // scores batch (z)
    const long long ZV = (long long)NS * NDH;    // vavg batch (z)

    for (int l = 0; l < NL; l++) {
        const size_t oP1 = OFF_P1 + (size_t)l*512*ND;
        const size_t oP2 = OFF_P2 + (size_t)l*512*ND;
        const size_t oQ1 = OFF_Q1 + (size_t)l*ND*3*ND;
        const size_t oQ2 = OFF_Q2 + (size_t)l*ND*3*ND;
        const size_t oO  = OFF_O  + (size_t)l*ND*ND;
        const size_t oM1 = OFF_M1 + (size_t)l*ND*4*ND;
        const size_t oM2 = OFF_M2 + (size_t)l*4*ND*ND;

        adapt_kernel<<<1, 256>>>(U + (size_t)l * ND * 4, V + (size_t)l * 4 * ND, sigma + l, pad);
        ln_kernel<true, false, true><<<NTOK, 256>>>(px, g1 + l*ND, b1 + l*ND, pad, nullptr, nullptr, hh, hl);

        // x1p / x2p  (BN=64, 256 CTAs, 3-stage)
        mma_gemm<64,false,false,false,OUT_SPLIT,3><<<dim3(16,16), 256, SM_B64_S3>>>(
            hh, hl, ND, 0, 0, wh+oP1, wl+oP1, ND, 0, 0,
            bp1 + l*ND, nullptr, nullptr, x1h, x1l, ND, 0, 0, 512, 1.0f);
        mma_gemm<64,false,false,false,OUT_SPLIT,3><<<dim3(16,16), 256, SM_B64_S3>>>(
            hh+512, hl+512, ND, 0, 0, wh+oP2, wl+oP2, ND, 0, 0,
            bp2 + l*ND, nullptr, nullptr, x2h, x2l, ND, 0, 0, 512, 1.0f);

        // qkv (BN=128)
        mma_gemm<128,false,false,false,OUT_SPLIT,2><<<dim3(24,16), 256, SM_B128_S2>>>(
            x1h, x1l, ND, 0, 0, wh+oQ1, wl+oQ1, 3*ND, 0, 0,
            nullptr, nullptr, nullptr, q1h, q1l, 3*ND, 0, 0, ND, 1.0f);
        mma_gemm<128,false,false,false,OUT_SPLIT,2><<<dim3(24,16), 256, SM_B128_S2>>>(
            x2h, x2l, ND, 0, 0, wh+oQ2, wl+oQ2, 3*ND, 0, 0,
            nullptr, nullptr, nullptr, q2h, q2l, 3*ND, 0, 0, ND, 1.0f);

        // scores (TRANSB, fp32 out)
        mma_gemm<128,true,false,false,OUT_F32,2><<<dim3(8,8,32), 256, SM_SC_S2>>>(
            q1h, q1l, 3072, ZA, 64, q1h+ND, q1l+ND, 3072, ZA, 64,
            nullptr, nullptr, ps1, nullptr, nullptr, NS, 16*ZS, ZS, NDH, ATT_SCALE);
        mma_gemm<128,true,false,false,OUT_F32,2><<<dim3(8,8,32), 256, SM_SC_S2>>>(
            q2h, q2l, 3072, ZA, 64, q2h+ND, q2l+ND, 3072, ZA, 64,
            nullptr, nullptr, ps2, nullptr, nullptr, NS, 16*ZS, ZS, NDH, ATT_SCALE);

        softmax_diff_kernel<<<NB*NH*NS, 256>>>(ps1, ps2, dh, dl);
        vavg_kernel<<<32*NS*NDH/256, 256>>>(q1h, q1l, q2h, q2l, vah, val);

        // PV (BN=64, split out, written as [b,s,h*64+d])
        mma_gemm<64,false,false,false,OUT_SPLIT,3><<<dim3(1,8,32), 256, SM_B64_S3>>>(
            dh, dl, NS, 16*ZS, ZS, vah, val, NDH, 16*ZV, ZV,
            nullptr, nullptr, nullptr, ph_, pl_, ND, (long long)NS*ND, 64, NS, 1.0f);

        // out proj (BN=64, fp32) + post-LN + residual
        mma_gemm<64,false,false,false,OUT_F32,3><<<dim3(16,16), 256, SM_B64_S3>>>(
            ph_, pl_, ND, 0, 0, wh+oO, wl+oO, ND, 0, 0,
            bo + l*ND, nullptr, ptmp, nullptr, nullptr, ND, 0, 0, ND, 1.0f);
        ln_kernel<false, true, false><<<NTOK, 256>>>(ptmp, gO + l*ND, bO + l*ND, nullptr, px, px, nullptr, nullptr);

        // MLP
        ln_kernel<false, false, true><<<NTOK, 256>>>(px, g2 + l*ND, b2 + l*ND, nullptr, nullptr, nullptr, hh, hl);
        mma_gemm<128,false,true,false,OUT_SPLIT,2><<<dim3(32,16), 256, SM_B128_S2>>>(
            hh, hl, ND, 0, 0, wh+oM1, wl+oM1, 4*ND, 0, 0,
            bm1 + (size_t)l*4*ND, nullptr, nullptr, mh, ml, 4*ND, 0, 0, ND, 1.0f);
        mma_gemm<64,false,false,true,OUT_F32,3><<<dim3(16,16), 256, SM_B64_S3>>>(
            mh, ml, 4*ND, 0, 0, wh+oM2, wl+oM2, ND, 0, 0,
            bm2 + l*ND, px, px, nullptr, nullptr, ND, 0, 0, 4*ND, 1.0f);
    }

    ln_kernel<false, false, false><<<NTOK, 256>>>(px, gf, bf, nullptr, nullptr, (float*)d_out, nullptr, nullptr);
}

// round 8
// speedup vs baseline: 3.0624x; 1.0375x over previous
#include <cuda_runtime.h>
#include <cuda_fp16.h>
#include <math.h>
#include <stdint.h>

#define NL 4
#define NB 2
#define NS 1024
#define ND 1024
#define NH 16
#define NDH 64
#define NTOK (NB*NS)        // 2048
#define ATT_SCALE 0.125f
#define LN_EPS 1e-5f

typedef unsigned short u16;

// ---------------- scratch (static device globals: alloc-free) ----------------
__device__ float g_x    [NTOK*ND];
__device__ float g_tmp  [NTOK*ND];
__device__ float g_s1   [(size_t)NB*NH*NS*NS];   // scores fp32 (134 MB)
__device__ float g_s2   [(size_t)NB*NH*NS*NS];
__device__ float g_adapt[ND];

// split fp16 weights, grouped by TYPE (contiguous across layers)
#define WTOT 67108864ULL
#define OFF_P1 0ULL
#define OFF_P2 2097152ULL
#define OFF_Q1 4194304ULL
#define OFF_Q2 16777216ULL
#define OFF_O  29360128ULL
#define OFF_M1 33554432ULL
#define OFF_M2 50331648ULL
__device__ u16 g_wh [WTOT];
__device__ u16 g_wl [WTOT];
__device__ u16 g_hh [NTOK*ND],      g_hl [NTOK*ND];       // LN out
__device__ u16 g_x1h[NTOK*ND],      g_x1l[NTOK*ND];
__device__ u16 g_x2h[NTOK*ND],      g_x2l[NTOK*ND];
__device__ u16 g_q1h[NTOK*3*ND],    g_q1l[NTOK*3*ND];
__device__ u16 g_q2h[NTOK*3*ND],    g_q2l[NTOK*3*ND];
__device__ u16 g_dh [(size_t)32*NS*NS], g_dl[(size_t)32*NS*NS]; // softmax diff
__device__ u16 g_vah[32*NS*NDH],    g_val[32*NS*NDH];
__device__ u16 g_ph [NTOK*ND],      g_pl [NTOK*ND];       // attn out
__device__ u16 g_mh [NTOK*4*ND],    g_ml [NTOK*4*ND];     // gelu out

// ---------------- helpers ----------------
__device__ __forceinline__ uint32_t smem_u32(const void* p) {
    uint32_t a;
    asm("{ .reg .u64 t; cvta.to.shared.u64 t, %1; cvt.u32.u64 %0, t; }" : "=r"(a) : "l"(p));
    return a;
}
__device__ __forceinline__ void splitw(float v, u16& h, u16& l) {
    __half hh = __float2half_rn(v);
    h = __half_as_ushort(hh);
    l = __half_as_ushort(__float2half_rn(v - __half2float(hh)));
}
__device__ __forceinline__ float joinw(u16 h, u16 l) {
    return __half2float(__ushort_as_half(h)) + __half2float(__ushort_as_half(l));
}
__device__ __forceinline__ void mma16(float* c, const uint32_t* a, const uint32_t* b) {
    asm volatile(
        "mma.sync.aligned.m16n8k16.row.col.f32.f16.f16.f32 "
        "{%0,%1,%2,%3},{%4,%5,%6,%7},{%8,%9},{%0,%1,%2,%3};\n"
        : "+f"(c[0]), "+f"(c[1]), "+f"(c[2]), "+f"(c[3])
        : "r"(a[0]), "r"(a[1]), "r"(a[2]), "r"(a[3]), "r"(b[0]), "r"(b[1]));
}
__device__ __forceinline__ void ldsm4t(uint32_t* r, uint32_t addr) {
    asm volatile("ldmatrix.sync.aligned.m8n8.x4.trans.shared.b16 {%0,%1,%2,%3}, [%4];"
        : "=r"(r[0]), "=r"(r[1]), "=r"(r[2]), "=r"(r[3]) : "r"(addr));
}
__device__ __forceinline__ void ldsm4(uint32_t* r, uint32_t addr) {
    asm volatile("ldmatrix.sync.aligned.m8n8.x4.shared.b16 {%0,%1,%2,%3}, [%4];"
        : "=r"(r[0]), "=r"(r[1]), "=r"(r[2]), "=r"(r[3]) : "r"(addr));
}
__device__ __forceinline__ void cpa16(uint32_t dst, const void* src) {
    asm volatile("cp.async.cg.shared.global [%0], [%1], 16;" :: "r"(dst), "l"(src));
}
__device__ __forceinline__ void cpacommit() { asm volatile("cp.async.commit_group;"); }
template<int N> __device__ __forceinline__ void cpawait() {
    asm volatile("cp.async.wait_group %0;" :: "n"(N));
}

template<bool MAXRED>
__device__ __forceinline__ float blk_reduce(float v, float* red) {
    int t = threadIdx.x;  // 256 threads
    red[t] = v; __syncthreads();
    #pragma unroll
    for (int o = 128; o > 0; o >>= 1) {
        if (t < o) red[t] = MAXRED ? fmaxf(red[t], red[t + o]) : (red[t] + red[t + o]);
        __syncthreads();
    }
    float r = red[0];
    __syncthreads();
    return r;
}

// ---------------- tiny kernels ----------------
__global__ void copy_kernel(const float* __restrict__ in, float* __restrict__ out, int n) {
    int i = blockIdx.x * 256 + threadIdx.x;
    if (i < n) out[i] = in[i];
}

// vectorized split (n multiple of 4)
__global__ void wsplit_kernel(const float* __restrict__ w, u16* __restrict__ h,
                              u16* __restrict__ l, size_t n) {
    for (size_t i = ((size_t)blockIdx.x * 256 + threadIdx.x) * 4; i < n;
         i += (size_t)gridDim.x * 1024) {
        float4 v = *(const float4*)(w + i);
        u16 h0,l0,h1,l1,h2,l2,h3,l3;
        splitw(v.x,h0,l0); splitw(v.y,h1,l1); splitw(v.z,h2,l2); splitw(v.w,h3,l3);
        *(uint2*)(h + i) = make_uint2((uint32_t)h0 | ((uint32_t)h1<<16),
                                      (uint32_t)h2 | ((uint32_t)h3<<16));
        *(uint2*)(l + i) = make_uint2((uint32_t)l0 | ((uint32_t)l1<<16),
                                      (uint32_t)l2 | ((uint32_t)l3<<16));
    }
}

__global__ void adapt_kernel(const float* __restrict__ U, const float* __restrict__ V,
                             const float* __restrict__ sigma, float* __restrict__ adapt) {
    __shared__ float red[256];
    __shared__ float vsum[4];
    int t = threadIdx.x;
    for (int r = 0; r < 4; r++) {
        float s = 0.f;
        for (int j = t; j < ND; j += 256) s += V[r * ND + j];
        s = blk_reduce<false>(s, red);
        if (t == 0) vsum[r] = s;
        __syncthreads();
    }
    float sg = sigma[0];
    for (int i = t; i < ND; i += 256) {
        float a = 0.f;
        #pragma unroll
        for (int r = 0; r < 4; r++) a += U[i * 4 + r] * vsum[r];
        adapt[i] = a * sg;
    }
}

template<bool ADD_ADAPT, bool RES, bool SPLIT>
__global__ void ln_kernel(const float* __restrict__ in, const float* __restrict__ g,
                          const float* __restrict__ b, const float* __restrict__ adapt,
                          const float* __restrict__ res, float* __restrict__ out,
                          u16* __restrict__ oh, u16* __restrict__ ol) {
    __shared__ float red[256];
    int row = blockIdx.x, t = threadIdx.x;
    const float* rin = in + (size_t)row * ND;
    float v[4];
    #pragma unroll
    for (int i = 0; i < 4; i++) v[i] = rin[t + i * 256];
    float s = v[0] + v[1] + v[2] + v[3];
    float mean = blk_reduce<false>(s, red) * (1.0f / ND);
    float sq = 0.f;
    #pragma unroll
    for (int i = 0; i < 4; i++) { float d = v[i] - mean; sq += d * d; }
    float var = blk_reduce<false>(sq, red) * (1.0f / ND);
    float inv = rsqrtf(var + LN_EPS);
    #pragma unroll
    for (int i = 0; i < 4; i++) {
        int c = t + i * 256;
        float o = (v[i] - mean) * inv * g[c] + b[c];
        if (ADD_ADAPT) o += adapt[c];
        if (RES)       o += res[(size_t)row * ND + c];
        size_t idx = (size_t)row * ND + c;
        if (SPLIT) { u16 hh, ll; splitw(o, hh, ll); oh[idx] = hh; ol[idx] = ll; }
        else out[idx] = o;
    }
}

__global__ void softmax_diff_kernel(const float* __restrict__ s1, const float* __restrict__ s2,
                                    u16* __restrict__ dh, u16* __restrict__ dl) {
    __shared__ float red[256];
    size_t row = blockIdx.x;
    const float* r1 = s1 + row * NS;
    const float* r2 = s2 + row * NS;
    int t = threadIdx.x;
    float v1[4], v2[4];
    #pragma unroll
    for (int i = 0; i < 4; i++) { v1[i] = r1[t + i * 256]; v2[i] = r2[t + i * 256]; }
    float m1 = fmaxf(fmaxf(v1[0], v1[1]), fmaxf(v1[2], v1[3]));
    float m2 = fmaxf(fmaxf(v2[0], v2[1]), fmaxf(v2[2], v2[3]));
    m1 = blk_reduce<true>(m1, red);
    m2 = blk_reduce<true>(m2, red);
    float e1 = 0.f, e2 = 0.f;
    #pragma unroll
    for (int i = 0; i < 4; i++) {
        v1[i] = __expf(v1[i] - m1); e1 += v1[i];
        v2[i] = __expf(v2[i] - m2); e2 += v2[i];
    }
    e1 = blk_reduce<false>(e1, red);
    e2 = blk_reduce<false>(e2, red);
    float i1 = 1.0f / e1, i2 = 1.0f / e2;
    #pragma unroll
    for (int i = 0; i < 4; i++) {
        float d = v1[i] * i1 - v2[i] * i2;
        u16 hh, ll; splitw(d, hh, ll);
        dh[row * NS + t + i * 256] = hh;
        dl[row * NS + t + i * 256] = ll;
    }
}

__global__ void vavg_kernel(const u16* __restrict__ q1h, const u16* __restrict__ q1l,
                            const u16* __restrict__ q2h, const u16* __restrict__ q2l,
                            u16* __restrict__ oh, u16* __restrict__ ol) {
    int i = blockIdx.x * 256 + threadIdx.x;  // 32*NS*64
    int d = i & 63;
    int k = (i >> 6) & (NS - 1);
    int z = i >> 16;
    int b = z >> 4, h = z & 15;
    size_t src = ((size_t)(b * NS + k)) * 3072 + 2048 + h * 64 + d;
    float v = 0.5f * (joinw(q1h[src], q1l[src]) + joinw(q2h[src], q2l[src]));
    u16 hh, ll; splitw(v, hh, ll);
    oh[i] = hh; ol[i] = ll;
}

// ---------------- split-fp16 mma.sync GEMM, NSTG-stage cp.async pipeline -----
// All fragment loads via ldmatrix (A non-trans x4; B trans-x4 or non-trans x4).
#define OUT_F32 0
#define OUT_SPLIT 1

template<int BN, bool TRANSB, bool GELU, bool RES, int OUTM, int NSTG>
__global__ void __launch_bounds__(256, 2) mma_gemm(
    const u16* __restrict__ Ahg, const u16* __restrict__ Alg, int lda, long long aO, long long aI,
    const u16* __restrict__ Bhg, const u16* __restrict__ Blg, int ldb, long long bO, long long bI,
    const float* __restrict__ bias, const float* __restrict__ res,
    float* __restrict__ Cf, u16* __restrict__ Chi, u16* __restrict__ Clo,
    int ldc, long long cO, long long cI, int K, float alpha)
{
    constexpr int AP = 40;
    constexpr int ASZ = 128 * AP;
    constexpr int BROWS = TRANSB ? BN : 32;
    constexpr int BP = TRANSB ? 40 : (BN + 8);
    constexpr int BSZ = BROWS * BP;
    constexpr int STG = 2 * ASZ + 2 * BSZ;
    extern __shared__ u16 sm[];

    const int t = threadIdx.x;
    const int w = t >> 5, lane = t & 31;
    const int g = lane >> 2, th = lane & 3;
    const int m0 = blockIdx.y * 128, n0 = blockIdx.x * BN;
    const int z = blockIdx.z;
    const long long offA = (long long)(z >> 4) * aO + (long long)(z & 15) * aI;
    const long long offB = (long long)(z >> 4) * bO + (long long)(z & 15) * bI;
    const long long offC = (long long)(z >> 4) * cO + (long long)(z & 15) * cI;
    const u16* Ah_g = Ahg + offA;
    const u16* Al_g = Alg + offA;
    const u16* Bh_g = Bhg + offB;
    const u16* Bl_g = Blg + offB;

    constexpr int MFRAG = (BN == 128) ? 4 : 2;
    const int wm = (BN == 128) ? ((w >> 2) * 64) : ((w >> 1) * 32);
    const int wn = (BN == 128) ? ((w & 3) * 32) : ((w & 1) * 32);

    // ldmatrix lane roles
    const int lrow = (lane & 7) + ((lane & 8) ? 8 : 0);       // trans-B (weights)
    const int lcol = (lane & 16) ? 8 : 0;
    const int arow = lane & 15;                                // A non-trans
    const int acol = (lane >> 4) << 3;
    const int tb_n  = ((lane >> 4) << 3) + (lane & 7);         // TRANSB non-trans: n offset within 2 frags... (j + jj)*8 + (lane&7)
    const int tb_c  = ((lane >> 3) & 1) << 3;                  // k half select
    const uint32_t smbase = smem_u32(sm);

    float acc[MFRAG][4][4] = {};

    auto issue = [&](int kt, int s) {
        const uint32_t ah = smbase + (uint32_t)(s * STG) * 2;
        const uint32_t al = ah + ASZ * 2;
        const uint32_t bh = al + ASZ * 2;
        const uint32_t bl = bh + BSZ * 2;
        #pragma unroll
        for (int c = t; c < 512; c += 256) {
            int row = c >> 2, k8 = (c & 3) * 8;
            size_t gidx = (size_t)(m0 + row) * lda + kt + k8;
            uint32_t doff = (uint32_t)(row * AP + k8) * 2;
            cpa16(ah + doff, Ah_g + gidx);
            cpa16(al + doff, Al_g + gidx);
        }
        if (TRANSB) {
            #pragma unroll
            for (int c = t; c < BN * 4; c += 256) {
                int row = c >> 2, k8 = (c & 3) * 8;
                size_t gidx = (size_t)(n0 + row) * ldb + kt + k8;
                uint32_t doff = (uint32_t)(row * BP + k8) * 2;
                cpa16(bh + doff, Bh_g + gidx);
                cpa16(bl + doff, Bl_g + gidx);
            }
        } else {
            constexpr int CPR = BN / 8;
            #pragma unroll
            for (int c = t; c < 32 * CPR; c += 256) {
                int row = c / CPR, n8 = (c % CPR) * 8;
                size_t gidx = (size_t)(kt + row) * ldb + n0 + n8;
                uint32_t doff = (uint32_t)(row * BP + n8) * 2;
                cpa16(bh + doff, Bh_g + gidx);
                cpa16(bl + doff, Bl_g + gidx);
            }
        }
        cpacommit();
    };

    const int tiles = K >> 5;
    #pragma unroll
    for (int p = 0; p < NSTG - 1 && p < tiles; p++) issue(p << 5, p % NSTG);

    for (int i = 0; i < tiles; i++) {
        cpawait<NSTG - 2>();
        __syncthreads();
        {
            int nx = i + NSTG - 1;
            if (nx < tiles) issue(nx << 5, nx % NSTG);
        }
        const int s = i % NSTG;
        const uint32_t ah_base = smbase + (uint32_t)(s * STG) * 2;
        const uint32_t al_base = ah_base + ASZ * 2;
        const uint32_t bh_base = al_base + ASZ * 2;
        const uint32_t bl_base = bh_base + BSZ * 2;

        #pragma unroll
        for (int ks = 0; ks < 2; ks++) {
            int ko = ks * 16;
            uint32_t bhf[4][2], blf[4][2];
            if (TRANSB) {
                // non-trans ldmatrix on Bs[n][k]: 2 frag-pairs per x4
                #pragma unroll
                for (int pr = 0; pr < 2; pr++) {
                    int nrow = wn + pr * 16 + tb_n;
                    uint32_t off = (uint32_t)((nrow * BP + ko + tb_c) * 2);
                    uint32_t r[4];
                    ldsm4(r, bh_base + off);
                    bhf[pr*2][0]=r[0]; bhf[pr*2][1]=r[1]; bhf[pr*2+1][0]=r[2]; bhf[pr*2+1][1]=r[3];
                    ldsm4(r, bl_base + off);
                    blf[pr*2][0]=r[0]; blf[pr*2][1]=r[1]; blf[pr*2+1][0]=r[2]; blf[pr*2+1][1]=r[3];
                }
            } else {
                // trans ldmatrix on Bs[k][n]
                #pragma unroll
                for (int pr = 0; pr < 2; pr++) {
                    uint32_t off = (uint32_t)(((ko + lrow) * BP + wn + pr * 16 + lcol) * 2);
                    uint32_t r[4];
                    ldsm4t(r, bh_base + off);
                    bhf[pr*2][0]=r[0]; bhf[pr*2][1]=r[1]; bhf[pr*2+1][0]=r[2]; bhf[pr*2+1][1]=r[3];
                    ldsm4t(r, bl_base + off);
                    blf[pr*2][0]=r[0]; blf[pr*2][1]=r[1]; blf[pr*2+1][0]=r[2]; blf[pr*2+1][1]=r[3];
                }
            }
            // A hi fragments via non-trans ldmatrix; hi*hi + hi*lo
            uint32_t af[MFRAG][4];
            #pragma unroll
            for (int mi = 0; mi < MFRAG; mi++) {
                int mr = wm + mi * 16 + arow;
                ldsm4(af[mi], ah_base + (uint32_t)((mr * AP + ko + acol) * 2));
            }
            #pragma unroll
            for (int mi = 0; mi < MFRAG; mi++)
                #pragma unroll
                for (int ni = 0; ni < 4; ni++) {
                    mma16(acc[mi][ni], af[mi], bhf[ni]);
                    mma16(acc[mi][ni], af[mi], blf[ni]);
                }
            // A lo fragments; lo*hi
            #pragma unroll
            for (int mi = 0; mi < MFRAG; mi++) {
                int mr = wm + mi * 16 + arow;
                ldsm4(af[mi], al_base + (uint32_t)((mr * AP + ko + acol) * 2));
            }
            #pragma unroll
            for (int mi = 0; mi < MFRAG; mi++)
                #pragma unroll
                for (int ni = 0; ni < 4; ni++)
                    mma16(acc[mi][ni], af[mi], bhf[ni]);
        }
    }

    // ---- epilogue ----
    #pragma unroll
    for (int mi = 0; mi < MFRAG; mi++) {
        #pragma unroll
        for (int ni = 0; ni < 4; ni++) {
            int col = n0 + wn + ni * 8 + th * 2;
            #pragma unroll
            for (int half = 0; half < 2; half++) {
                int row = m0 + wm + mi * 16 + g + half * 8;
                float v0 = acc[mi][ni][half * 2 + 0] * alpha;
                float v1 = acc[mi][ni][half * 2 + 1] * alpha;
                if (bias) { v0 += bias[col]; v1 += bias[col + 1]; }
                if (RES) {
                    v0 += res[(size_t)row * ldc + col];
                    v1 += res[(size_t)row * ldc + col + 1];
                }
                if (GELU) {
                    v0 = 0.5f * v0 * (1.0f + erff(v0 * 0.70710678118654752f));
                    v1 = 0.5f * v1 * (1.0f + erff(v1 * 0.70710678118654752f));
                }
                size_t idx = offC + (size_t)row * ldc + col;
                if (OUTM == OUT_SPLIT) {
                    u16 h0, l0, h1, l1;
                    splitw(v0, h0, l0); splitw(v1, h1, l1);
                    *(uint32_t*)&Chi[idx] = (uint32_t)h0 | ((uint32_t)h1 << 16);
                    *(uint32_t*)&Clo[idx] = (uint32_t)l0 | ((uint32_t)l1 << 16);
                } else {
                    *(float2*)&Cf[idx] = make_float2(v0, v1);
                }
            }
        }
    }
}

// ---------------- host orchestration ----------------
extern "C" void kernel_launch(void* const* d_in, const int* in_sizes, int n_in,
                              void* d_out, int out_size) {
    (void)in_sizes; (void)n_in; (void)out_size;
    const float* x     = (const float*)d_in[0];
    const float* sigma = (const float*)d_in[1];
    const float* U     = (const float*)d_in[2];
    const float* V     = (const float*)d_in[3];
    const float* Wqkv1 = (const float*)d_in[4];
    const float* Wqkv2 = (const float*)d_in[5];
    const float* Wp1   = (const float*)d_in[6];
    const float* bp1   = (const float*)d_in[7];
    const float* Wp2   = (const float*)d_in[8];
    const float* bp2   = (const float*)d_in[9];
    const float* Wo    = (const float*)d_in[10];
    const float* bo    = (const float*)d_in[11];
    const float* gO    = (const float*)d_in[12];
    const float* bO    = (const float*)d_in[13];
    const float* g1    = (const float*)d_in[14];
    const float* b1    = (const float*)d_in[15];
    const float* g2    = (const float*)d_in[16];
    const float* b2    = (const float*)d_in[17];
    const float* Wm1   = (const float*)d_in[18];
    const float* bm1   = (const float*)d_in[19];
    const float* Wm2   = (const float*)d_in[20];
    const float* bm2   = (const float*)d_in[21];
    const float* gf    = (const float*)d_in[22];
    const float* bf    = (const float*)d_in[23];

    float *px, *ptmp, *ps1, *ps2, *pad;
    u16 *wh, *wl, *hh, *hl, *x1h, *x1l, *x2h, *x2l, *q1h, *q1l, *q2h, *q2l;
    u16 *dh, *dl, *vah, *val, *ph_, *pl_, *mh, *ml;
    cudaGetSymbolAddress((void**)&px,   g_x);
    cudaGetSymbolAddress((void**)&ptmp, g_tmp);
    cudaGetSymbolAddress((void**)&ps1,  g_s1);
    cudaGetSymbolAddress((void**)&ps2,  g_s2);
    cudaGetSymbolAddress((void**)&pad,  g_adapt);
    cudaGetSymbolAddress((void**)&wh,   g_wh);
    cudaGetSymbolAddress((void**)&wl,   g_wl);
    cudaGetSymbolAddress((void**)&hh,   g_hh);
    cudaGetSymbolAddress((void**)&hl,   g_hl);
    cudaGetSymbolAddress((void**)&x1h,  g_x1h);
    cudaGetSymbolAddress((void**)&x1l,  g_x1l);
    cudaGetSymbolAddress((void**)&x2h,  g_x2h);
    cudaGetSymbolAddress((void**)&x2l,  g_x2l);
    cudaGetSymbolAddress((void**)&q1h,  g_q1h);
    cudaGetSymbolAddress((void**)&q1l,  g_q1l);
    cudaGetSymbolAddress((void**)&q2h,  g_q2h);
    cudaGetSymbolAddress((void**)&q2l,  g_q2l);
    cudaGetSymbolAddress((void**)&dh,   g_dh);
    cudaGetSymbolAddress((void**)&dl,   g_dl);
    cudaGetSymbolAddress((void**)&vah,  g_vah);
    cudaGetSymbolAddress((void**)&val,  g_val);
    cudaGetSymbolAddress((void**)&ph_,  g_ph);
    cudaGetSymbolAddress((void**)&pl_,  g_pl);
    cudaGetSymbolAddress((void**)&mh,   g_mh);
    cudaGetSymbolAddress((void**)&ml,   g_ml);

    // dynamic smem sizes (bytes): NSTG * STG halves * 2
    const int SM_B128_S2 = 2 * (2*128*40 + 2*32*136) * 2;   // 75776
    const int SM_B64_S3  = 3 * (2*128*40 + 2*32*72)  * 2;   // 89088
    const int SM_SC_S2   = 2 * (2*128*40 + 2*128*40) * 2;   // 81920
    cudaFuncSetAttribute((const void*)mma_gemm<64, false,false,false,OUT_SPLIT,3>, cudaFuncAttributeMaxDynamicSharedMemorySize, SM_B64_S3);
    cudaFuncSetAttribute((const void*)mma_gemm<64, false,false,false,OUT_F32,  3>, cudaFuncAttributeMaxDynamicSharedMemorySize, SM_B64_S3);
    cudaFuncSetAttribute((const void*)mma_gemm<64, false,false,true, OUT_F32,  3>, cudaFuncAttributeMaxDynamicSharedMemorySize, SM_B64_S3);
    cudaFuncSetAttribute((const void*)mma_gemm<128,false,false,false,OUT_SPLIT,2>, cudaFuncAttributeMaxDynamicSharedMemorySize, SM_B128_S2);
    cudaFuncSetAttribute((const void*)mma_gemm<128,false,true, false,OUT_SPLIT,2>, cudaFuncAttributeMaxDynamicSharedMemorySize, SM_B128_S2);
    cudaFuncSetAttribute((const void*)mma_gemm<128,true, false,false,OUT_F32,  2>, cudaFuncAttributeMaxDynamicSharedMemorySize, SM_SC_S2);

    copy_kernel<<<NTOK * ND / 256, 256>>>(x, px, NTOK * ND);

    // pre-split weights, grouped by type (7 launches)
    wsplit_kernel<<<2048, 256>>>(Wp1,   wh + OFF_P1, wl + OFF_P1, (size_t)NL*512*ND);
    wsplit_kernel<<<2048, 256>>>(Wp2,   wh + OFF_P2, wl + OFF_P2, (size_t)NL*512*ND);
    wsplit_kernel<<<4096, 256>>>(Wqkv1, wh + OFF_Q1, wl + OFF_Q1, (size_t)NL*ND*3*ND);
    wsplit_kernel<<<4096, 256>>>(Wqkv2, wh + OFF_Q2, wl + OFF_Q2, (size_t)NL*ND*3*ND);
    wsplit_kernel<<<2048, 256>>>(Wo,    wh + OFF_O,  wl + OFF_O,  (size_t)NL*ND*ND);
    wsplit_kernel<<<4096, 256>>>(Wm1,   wh + OFF_M1, wl + OFF_M1, (size_t)NL*ND*4*ND);
    wsplit_kernel<<<4096, 256>>>(Wm2,   wh + OFF_M2, wl + OFF_M2, (size_t)NL*4*ND*ND);

    const long long ZA = (long long)NS * 3072;   // qkv batch stride (b)
    const long long ZS = (long long)NS * NS;     // scores batch (z)
    const long long ZV = (long long)NS * NDH;    // vavg batch (z)

    for (int l = 0; l < NL; l++) {
        const size_t oP1 = OFF_P1 + (size_t)l*512*ND;
        const size_t oP2 = OFF_P2 + (size_t)l*512*ND;
        const size_t oQ1 = OFF_Q1 + (size_t)l*ND*3*ND;
        const size_t oQ2 = OFF_Q2 + (size_t)l*ND*3*ND;
        const size_t oO  = OFF_O  + (size_t)l*ND*ND;
        const size_t oM1 = OFF_M1 + (size_t)l*ND*4*ND;
        const size_t oM2 = OFF_M2 + (size_t)l*4*ND*ND;

        adapt_kernel<<<1, 256>>>(U + (size_t)l * ND * 4, V + (size_t)l * 4 * ND, sigma + l, pad);
        ln_kernel<true, false, true><<<NTOK, 256>>>(px, g1 + l*ND, b1 + l*ND, pad, nullptr, nullptr, hh, hl);

        // x1p / x2p  (BN=64, 256 CTAs, 3-stage)
        mma_gemm<64,false,false,false,OUT_SPLIT,3><<<dim3(16,16), 256, SM_B64_S3>>>(
            hh, hl, ND, 0, 0, wh+oP1, wl+oP1, ND, 0, 0,
            bp1 + l*ND, nullptr, nullptr, x1h, x1l, ND, 0, 0, 512, 1.0f);
        mma_gemm<64,false,false,false,OUT_SPLIT,3><<<dim3(16,16), 256, SM_B64_S3>>>(
            hh+512, hl+512, ND, 0, 0, wh+oP2, wl+oP2, ND, 0, 0,
            bp2 + l*ND, nullptr, nullptr, x2h, x2l, ND, 0, 0, 512, 1.0f);

        // qkv (BN=128)
        mma_gemm<128,false,false,false,OUT_SPLIT,2><<<dim3(24,16), 256, SM_B128_S2>>>(
            x1h, x1l, ND, 0, 0, wh+oQ1, wl+oQ1, 3*ND, 0, 0,
            nullptr, nullptr, nullptr, q1h, q1l, 3*ND, 0, 0, ND, 1.0f);
        mma_gemm<128,false,false,false,OUT_SPLIT,2><<<dim3(24,16), 256, SM_B128_S2>>>(
            x2h, x2l, ND, 0, 0, wh+oQ2, wl+oQ2, 3*ND, 0, 0,
            nullptr, nullptr, nullptr, q2h, q2l, 3*ND, 0, 0, ND, 1.0f);

        // scores (TRANSB, fp32 out)
        mma_gemm<128,true,false,false,OUT_F32,2><<<dim3(8,8,32), 256, SM_SC_S2>>>(
            q1h, q1l, 3072, ZA, 64, q1h+ND, q1l+ND, 3072, ZA, 64,
            nullptr, nullptr, ps1, nullptr, nullptr, NS, 16*ZS, ZS, NDH, ATT_SCALE);
        mma_gemm<128,true,false,false,OUT_F32,2><<<dim3(8,8,32), 256, SM_SC_S2>>>(
            q2h, q2l, 3072, ZA, 64, q2h+ND, q2l+ND, 3072, ZA, 64,
            nullptr, nullptr, ps2, nullptr, nullptr, NS, 16*ZS, ZS, NDH, ATT_SCALE);

        softmax_diff_kernel<<<NB*NH*NS, 256>>>(ps1, ps2, dh, dl);
        vavg_kernel<<<32*NS*NDH/256, 256>>>(q1h, q1l, q2h, q2l, vah, val);

        // PV (BN=64, split out, written as [b,s,h*64+d])
        mma_gemm<64,false,false,false,OUT_SPLIT,3><<<dim3(1,8,32), 256, SM_B64_S3>>>(
            dh, dl, NS, 16*ZS, ZS, vah, val, NDH, 16*ZV, ZV,
            nullptr, nullptr, nullptr, ph_, pl_, ND, (long long)NS*ND, 64, NS, 1.0f);

        // out proj (BN=64, fp32) + post-LN + residual
        mma_gemm<64,false,false,false,OUT_F32,3><<<dim3(16,16), 256, SM_B64_S3>>>(
            ph_, pl_, ND, 0, 0, wh+oO, wl+oO, ND, 0, 0,
            bo + l*ND, nullptr, ptmp, nullptr, nullptr, ND, 0, 0, ND, 1.0f);
        ln_kernel<false, true, false><<<NTOK, 256>>>(ptmp, gO + l*ND, bO + l*ND, nullptr, px, px, nullptr, nullptr);

        // MLP
        ln_kernel<false, false, true><<<NTOK, 256>>>(px, g2 + l*ND, b2 + l*ND, nullptr, nullptr, nullptr, hh, hl);
        mma_gemm<128,false,true,false,OUT_SPLIT,2><<<dim3(32,16), 256, SM_B128_S2>>>(
            hh, hl, ND, 0, 0, wh+oM1, wl+oM1, 4*ND, 0, 0,
            bm1 + (size_t)l*4*ND, nullptr, nullptr, mh, ml, 4*ND, 0, 0, ND, 1.0f);
        mma_gemm<64,false,false,true,OUT_F32,3><<<dim3(16,16), 256, SM_B64_S3>>>(
            mh, ml, 4*ND, 0, 0, wh+oM2, wl+oM2, ND, 0, 0,
            bm2 + l*ND, px, px, nullptr, nullptr, ND, 0, 0, 4*ND, 1.0f);
    }

    ln_kernel<false, false, false><<<NTOK, 256>>>(px, gf, bf, nullptr, nullptr, (float*)d_out, nullptr, nullptr);
}